// round 5
// baseline (speedup 1.0000x reference)
#include <cuda_runtime.h>
#include <math.h>

#define NN 200000
#define NE 1600000
#define NB 1000
#define H  128

// ------------------------- device scratch (no allocs allowed) ----------------
__device__ float  g_xw [(size_t)NN * H];   // xW_gcn, later reused for h2
__device__ float  g_agg[(size_t)NN * H];   // GCN aggregate (pre-bias/relu)
__device__ float  g_h1 [(size_t)NN * H];   // h1
__device__ float  g_deg[NN];               // degree -> dinv (in place)
__device__ double g_stats[6 * H];          // sum0,sq0,sum1,sq1,sum2,sq2
__device__ float  g_W1f[H * H];            // BN0-folded W1
__device__ float  g_b1f[H];
__device__ float  g_W3a[H], g_W3b[H];
__device__ float  g_c;
__device__ float  g_gsum[NB], g_gcnt[NB];
__device__ int    g_is64;

// ------------------------- index dtype detection -----------------------------
__global__ void k_detect(const long long* __restrict__ ei) {
    if (threadIdx.x == 0) {
        int ok = 1;
        for (int i = 0; i < 128; i++) {
            long long v = ei[i];
            if (v < 0 || v >= NN) ok = 0;
        }
        g_is64 = ok;
    }
}

__global__ void k_init() {
    int i = blockIdx.x * blockDim.x + threadIdx.x;
    if (i < 6 * H) g_stats[i] = 0.0;
    if (i < NB) { g_gsum[i] = 0.f; g_gcnt[i] = 0.f; }
}

__global__ void k_deginit() {
    int i = blockIdx.x * blockDim.x + threadIdx.x;
    if (i < NN) g_deg[i] = 1.0f;               // self loop
}

__global__ void k_edgedeg(const long long* __restrict__ e64,
                          const int* __restrict__ e32) {
    int is64 = g_is64;
    for (int e = blockIdx.x * blockDim.x + threadIdx.x; e < NE;
         e += gridDim.x * blockDim.x) {
        int d = is64 ? (int)e64[NE + e] : e32[NE + e];
        atomicAdd(&g_deg[d], 1.0f);
    }
}

__global__ void k_dinv() {
    int i = blockIdx.x * blockDim.x + threadIdx.x;
    if (i < NN) g_deg[i] = rsqrtf(g_deg[i]);   // now dinv
}

// ------------------------- tf32 helpers --------------------------------------
__device__ __forceinline__ void mma8(float* c, const unsigned* a, const unsigned* b) {
    asm volatile(
        "mma.sync.aligned.m16n8k8.row.col.f32.tf32.tf32.f32 "
        "{%0,%1,%2,%3}, {%4,%5,%6,%7}, {%8,%9}, {%0,%1,%2,%3};"
        : "+f"(c[0]), "+f"(c[1]), "+f"(c[2]), "+f"(c[3])
        : "r"(a[0]), "r"(a[1]), "r"(a[2]), "r"(a[3]), "r"(b[0]), "r"(b[1]));
}

__device__ __forceinline__ void split4(float4 v, unsigned* h, unsigned* l) {
    float f[4] = {v.x, v.y, v.z, v.w};
#pragma unroll
    for (int j = 0; j < 4; j++) {
        unsigned hj;
        asm("cvt.rna.tf32.f32 %0, %1;" : "=r"(hj) : "f"(f[j]));
        h[j] = hj;
        l[j] = __float_as_uint(f[j] - __uint_as_float(hj));
    }
}

// ------------------------- 3xTF32 MMA GEMM: C[N,128] = A[N,K] @ W[K,128] -----
// BM=128, BK=16, 256 threads (8 warps: wm in 0..1 x wn in 0..3).
// Warp tile 64x32 via m16n8k8 frags; 3xTF32 (hi*hi + hi*lo + lo*hi).
// EPI 0: C -> g_xw and g_agg = C * dinv^2 (self-loop init).       (K=64)
// EPI 1: A = relu(g_agg + bgcn) on the fly (Ain = bgcn), W = g_W1f,
//        bias = g_b1f; C -> g_h1 = relu(C+bias); stats[2],[3].    (K=128)
// EPI 2: C -> g_xw = relu(C+bias); stats[4],[5].                  (K=32)
template<int K, int EPI>
__global__ void __launch_bounds__(256)
k_mma(const float* __restrict__ Ain, const float* __restrict__ Win,
      const float* __restrict__ biasin) {
    const float* A    = (EPI == 1) ? (const float*)g_agg : Ain;
    const float* W    = (EPI == 1) ? (const float*)g_W1f : Win;
    const float* bias = (EPI == 1) ? (const float*)g_b1f : biasin;
    const float* abias = Ain;   // only used when EPI==1 (= b_gcn)

    __shared__ unsigned As_hi[128 * 20], As_lo[128 * 20];   // [row][k] pad 20
    __shared__ unsigned Bf_hi[2048], Bf_lo[2048];           // fragment-major
    __shared__ float s_sum[H], s_sq[H];

    const int tid  = threadIdx.x;
    const int lane = tid & 31;
    const int wid  = tid >> 5;
    const int wm   = wid >> 2;            // 0..1 -> 64 rows
    const int wn   = wid & 3;             // 0..3 -> 32 cols
    const int gg   = lane >> 2;           // group id 0..7
    const int tg   = lane & 3;            // thread-in-group
    const int bm   = blockIdx.x * 128;

    if (EPI != 0 && tid < H) { s_sum[tid] = 0.f; s_sq[tid] = 0.f; }

    float acc[4][4][4];
#pragma unroll
    for (int i = 0; i < 4; i++)
#pragma unroll
        for (int j = 0; j < 4; j++)
#pragma unroll
            for (int q = 0; q < 4; q++) acc[i][j][q] = 0.f;

    // fill-phase coordinates
    const int arow = tid >> 2;   // + i*64
    const int ac4  = tid & 3;
    const int wr0  = tid >> 5;   // + i*8
    const int wc4  = tid & 31;

    float4 aR[2], wR[2];

    auto loadA = [&](int st) {
#pragma unroll
        for (int i = 0; i < 2; i++) {
            int gr = bm + arow + i * 64;
            int gk = st * 16 + ac4 * 4;
            float4 v = make_float4(0.f, 0.f, 0.f, 0.f);
            if (gr < NN) {
                v = *(const float4*)&A[(size_t)gr * K + gk];
                if (EPI == 1) {
                    float4 b4 = *(const float4*)&abias[gk];
                    v.x = fmaxf(v.x + b4.x, 0.f);
                    v.y = fmaxf(v.y + b4.y, 0.f);
                    v.z = fmaxf(v.z + b4.z, 0.f);
                    v.w = fmaxf(v.w + b4.w, 0.f);
                }
            }
            aR[i] = v;
        }
    };
    auto loadW = [&](int st) {
#pragma unroll
        for (int i = 0; i < 2; i++) {
            int r = wr0 + i * 8;
            wR[i] = *(const float4*)&W[(size_t)(st * 16 + r) * H + wc4 * 4];
        }
    };

    loadA(0); loadW(0);

    for (int st = 0; st < K / 16; st++) {
        // ---- stage STS (split hi/lo) ----
#pragma unroll
        for (int i = 0; i < 2; i++) {
            unsigned h[4], l[4];
            split4(aR[i], h, l);
            int row = arow + i * 64;
            *(uint4*)&As_hi[row * 20 + ac4 * 4] = make_uint4(h[0], h[1], h[2], h[3]);
            *(uint4*)&As_lo[row * 20 + ac4 * 4] = make_uint4(l[0], l[1], l[2], l[3]);
        }
#pragma unroll
        for (int i = 0; i < 2; i++) {
            unsigned h[4], l[4];
            split4(wR[i], h, l);
            int r = wr0 + i * 8;
#pragma unroll
            for (int j = 0; j < 4; j++) {
                int n = wc4 * 4 + j;
                int idx = (((r >> 3) * 16 + (n >> 3)) * 32 +
                           ((n & 7) * 4 + (r & 3))) * 2 + ((r >> 2) & 1);
                Bf_hi[idx] = h[j];
                Bf_lo[idx] = l[j];
            }
        }
        __syncthreads();
        if (st + 1 < K / 16) { loadA(st + 1); loadW(st + 1); }

        // ---- compute ----
#pragma unroll
        for (int k8 = 0; k8 < 2; k8++) {
            unsigned bh[4][2], bl[4][2];
#pragma unroll
            for (int nf = 0; nf < 4; nf++) {
                int bi = ((k8 * 16 + wn * 4 + nf) * 32 + lane) * 2;
                uint2 vh = *(const uint2*)&Bf_hi[bi];
                uint2 vl = *(const uint2*)&Bf_lo[bi];
                bh[nf][0] = vh.x; bh[nf][1] = vh.y;
                bl[nf][0] = vl.x; bl[nf][1] = vl.y;
            }
#pragma unroll
            for (int mf = 0; mf < 4; mf++) {
                int r0 = (wm * 64 + mf * 16 + gg) * 20 + k8 * 8 + tg;
                unsigned ah[4] = {As_hi[r0], As_hi[r0 + 160],
                                  As_hi[r0 + 4], As_hi[r0 + 164]};
                unsigned al[4] = {As_lo[r0], As_lo[r0 + 160],
                                  As_lo[r0 + 4], As_lo[r0 + 164]};
#pragma unroll
                for (int nf = 0; nf < 4; nf++) {
                    mma8(acc[mf][nf], ah, bh[nf]);
                    mma8(acc[mf][nf], ah, bl[nf]);
                    mma8(acc[mf][nf], al, bh[nf]);
                }
            }
        }
        __syncthreads();
    }

    // ---- epilogue ----
    if (EPI == 0) {
#pragma unroll
        for (int mf = 0; mf < 4; mf++) {
            int r0 = bm + wm * 64 + mf * 16 + gg;
            int r1 = r0 + 8;
            float d0 = (r0 < NN) ? g_deg[r0] : 0.f; d0 *= d0;
            float d1 = (r1 < NN) ? g_deg[r1] : 0.f; d1 *= d1;
#pragma unroll
            for (int nf = 0; nf < 4; nf++) {
                int c = wn * 32 + nf * 8 + tg * 2;
                if (r0 < NN) {
                    *(float2*)&g_xw [(size_t)r0 * H + c] =
                        make_float2(acc[mf][nf][0], acc[mf][nf][1]);
                    *(float2*)&g_agg[(size_t)r0 * H + c] =
                        make_float2(acc[mf][nf][0] * d0, acc[mf][nf][1] * d0);
                }
                if (r1 < NN) {
                    *(float2*)&g_xw [(size_t)r1 * H + c] =
                        make_float2(acc[mf][nf][2], acc[mf][nf][3]);
                    *(float2*)&g_agg[(size_t)r1 * H + c] =
                        make_float2(acc[mf][nf][2] * d1, acc[mf][nf][3] * d1);
                }
            }
        }
    } else {
        float* dst = (EPI == 1) ? (float*)g_h1 : (float*)g_xw;
        float fs[4][2] = {{0, 0}, {0, 0}, {0, 0}, {0, 0}};
        float fq[4][2] = {{0, 0}, {0, 0}, {0, 0}, {0, 0}};
#pragma unroll
        for (int mf = 0; mf < 4; mf++) {
            int r0 = bm + wm * 64 + mf * 16 + gg;
            int r1 = r0 + 8;
#pragma unroll
            for (int nf = 0; nf < 4; nf++) {
                int c = wn * 32 + nf * 8 + tg * 2;
                float2 bb = *(const float2*)&bias[c];
                float v0 = fmaxf(acc[mf][nf][0] + bb.x, 0.f);
                float v1 = fmaxf(acc[mf][nf][1] + bb.y, 0.f);
                float v2 = fmaxf(acc[mf][nf][2] + bb.x, 0.f);
                float v3 = fmaxf(acc[mf][nf][3] + bb.y, 0.f);
                if (r0 < NN) {
                    *(float2*)&dst[(size_t)r0 * H + c] = make_float2(v0, v1);
                    fs[nf][0] += v0; fs[nf][1] += v1;
                    fq[nf][0] += v0 * v0; fq[nf][1] += v1 * v1;
                }
                if (r1 < NN) {
                    *(float2*)&dst[(size_t)r1 * H + c] = make_float2(v2, v3);
                    fs[nf][0] += v2; fs[nf][1] += v3;
                    fq[nf][0] += v2 * v2; fq[nf][1] += v3 * v3;
                }
            }
        }
#pragma unroll
        for (int o = 4; o <= 16; o <<= 1)
#pragma unroll
            for (int nf = 0; nf < 4; nf++)
#pragma unroll
                for (int j = 0; j < 2; j++) {
                    fs[nf][j] += __shfl_xor_sync(0xffffffffu, fs[nf][j], o);
                    fq[nf][j] += __shfl_xor_sync(0xffffffffu, fq[nf][j], o);
                }
        if (lane < 4) {
#pragma unroll
            for (int nf = 0; nf < 4; nf++) {
                int c = wn * 32 + nf * 8 + lane * 2;
                atomicAdd(&s_sum[c],     fs[nf][0]);
                atomicAdd(&s_sum[c + 1], fs[nf][1]);
                atomicAdd(&s_sq[c],      fq[nf][0]);
                atomicAdd(&s_sq[c + 1],  fq[nf][1]);
            }
        }
        __syncthreads();
        if (tid < H) {
            const int soff = (EPI == 1) ? 2 : 4;
            atomicAdd(&g_stats[(size_t)soff * H + tid], (double)s_sum[tid]);
            atomicAdd(&g_stats[(size_t)(soff + 1) * H + tid], (double)s_sq[tid]);
        }
    }
}

// ------------------------- edge scatter (GCN aggregate) ----------------------
__global__ void k_scatter(const long long* __restrict__ e64,
                          const int* __restrict__ e32) {
    const int is64   = g_is64;
    const int lane   = threadIdx.x & 31;
    const int warp   = (blockIdx.x * blockDim.x + threadIdx.x) >> 5;
    const int nwarps = (gridDim.x * blockDim.x) >> 5;
    for (int e = warp; e < NE; e += nwarps) {
        int s, d;
        if (is64) { s = (int)__ldg(&e64[e]); d = (int)__ldg(&e64[NE + e]); }
        else      { s = __ldg(&e32[e]);      d = __ldg(&e32[NE + e]); }
        float w = g_deg[s] * g_deg[d];
        float4 v = *(const float4*)&g_xw[(size_t)s * H + lane * 4];
        v.x *= w; v.y *= w; v.z *= w; v.w *= w;
        float* p = &g_agg[(size_t)d * H + lane * 4];
        asm volatile("red.global.add.v4.f32 [%0], {%1,%2,%3,%4};"
                     :: "l"(p), "f"(v.x), "f"(v.y), "f"(v.z), "f"(v.w)
                     : "memory");
    }
}

// ---------------- h0 stats only (h1 GEMM recomputes relu(agg+b) on load) -----
__global__ void k_h0(const float* __restrict__ bgcn) {
    const int f  = threadIdx.x & (H - 1);
    const float bv = bgcn[f];
    double s = 0.0, q = 0.0;
    const size_t total  = (size_t)NN * H;
    const size_t stride = (size_t)gridDim.x * blockDim.x;   // multiple of 128
    for (size_t i = (size_t)blockIdx.x * blockDim.x + threadIdx.x; i < total;
         i += stride) {
        float v = fmaxf(g_agg[i] + bv, 0.f);
        s += v; q += (double)v * v;
    }
    __shared__ double sS[256], sQ[256];
    sS[threadIdx.x] = s; sQ[threadIdx.x] = q;
    __syncthreads();
    if (threadIdx.x < H) {
        double ts = sS[threadIdx.x] + sS[threadIdx.x + H];
        double tq = sQ[threadIdx.x] + sQ[threadIdx.x + H];
        atomicAdd(&g_stats[0 * H + f], ts);
        atomicAdd(&g_stats[1 * H + f], tq);
    }
}

// ------------------------- fold BN0 into W1 ----------------------------------
__global__ void k_fold1(const float* __restrict__ g0, const float* __restrict__ be0,
                        const float* __restrict__ W1, const float* __restrict__ b1) {
    __shared__ float s0[H], t0[H];
    const int f = threadIdx.x;
    double mu  = g_stats[0 * H + f] / (double)NN;
    double var = g_stats[1 * H + f] / (double)NN - mu * mu;
    float  r   = (float)(1.0 / sqrt(var + 1e-5));
    float  sf  = g0[f] * r;
    float  tf  = be0[f] - (float)mu * sf;
    s0[f] = sf; t0[f] = tf;
    __syncthreads();
    float bacc = b1[f];
    for (int k = 0; k < H; k++) {
        float w = W1[k * H + f];
        g_W1f[k * H + f] = s0[k] * w;
        bacc += t0[k] * w;
    }
    g_b1f[f] = bacc;
}

// ------------------------- fold BN1/BN2 + W3 ---------------------------------
__global__ void k_fold3(const float* __restrict__ g1, const float* __restrict__ be1,
                        const float* __restrict__ g2, const float* __restrict__ be2,
                        const float* __restrict__ W3, const float* __restrict__ b3) {
    const int f = threadIdx.x;
    double mu1 = g_stats[2 * H + f] / (double)NN;
    double v1  = g_stats[3 * H + f] / (double)NN - mu1 * mu1;
    float  r1  = (float)(1.0 / sqrt(v1 + 1e-5));
    float  s1  = g1[f] * r1;
    float  t1  = be1[f] - (float)mu1 * s1;
    double mu2 = g_stats[4 * H + f] / (double)NN;
    double v2  = g_stats[5 * H + f] / (double)NN - mu2 * mu2;
    float  r2  = (float)(1.0 / sqrt(v2 + 1e-5));
    float  s2  = g2[f] * r2;
    float  t2  = be2[f] - (float)mu2 * s2;
    float w3a = W3[f], w3b = W3[H + f];
    g_W3a[f] = w3a * s1;
    g_W3b[f] = w3b * s2;
    __shared__ double red[H];
    red[f] = (double)(t1 * w3a) + (double)(t2 * w3b);
    __syncthreads();
    for (int o = 64; o > 0; o >>= 1) {
        if (f < o) red[f] += red[f + o];
        __syncthreads();
    }
    if (f == 0) g_c = (float)red[0] + b3[0];
}

// ------------------------- per-node scalar + segment sum ---------------------
__global__ void k_z(const long long* __restrict__ b64, const int* __restrict__ b32) {
    const int is64 = g_is64;
    const int lane = threadIdx.x & 31;
    const int n    = (blockIdx.x * blockDim.x + threadIdx.x) >> 5;
    if (n >= NN) return;
    float4 a  = *(const float4*)&g_h1[(size_t)n * H + lane * 4];
    float4 b  = *(const float4*)&g_xw[(size_t)n * H + lane * 4];   // h2
    float4 wa = *(const float4*)&g_W3a[lane * 4];
    float4 wb = *(const float4*)&g_W3b[lane * 4];
    float z = a.x * wa.x + a.y * wa.y + a.z * wa.z + a.w * wa.w +
              b.x * wb.x + b.y * wb.y + b.z * wb.z + b.w * wb.w;
#pragma unroll
    for (int o = 16; o > 0; o >>= 1) z += __shfl_xor_sync(0xffffffffu, z, o);
    if (lane == 0) {
        int g = is64 ? (int)b64[n] : b32[n];
        atomicAdd(&g_gsum[g], z);
        atomicAdd(&g_gcnt[g], 1.0f);
    }
}

__global__ void k_final(float* __restrict__ out, const float* __restrict__ b3) {
    int b = blockIdx.x * blockDim.x + threadIdx.x;
    if (b < NB) {
        float c = g_gcnt[b];
        out[b] = (c > 0.f) ? (g_gsum[b] / c + g_c) : b3[0];
    }
}

// ------------------------- launch ---------------------------------------------
extern "C" void kernel_launch(void* const* d_in, const int* in_sizes, int n_in,
                              void* d_out, int out_size) {
    const float* x      = (const float*)d_in[0];
    const float* action = (const float*)d_in[1];
    const float* W_gcn  = (const float*)d_in[2];
    const float* b_gcn  = (const float*)d_in[3];
    const float* g0     = (const float*)d_in[4];
    const float* be0    = (const float*)d_in[5];
    const float* W1     = (const float*)d_in[6];
    const float* b1     = (const float*)d_in[7];
    const float* g1     = (const float*)d_in[8];
    const float* be1    = (const float*)d_in[9];
    const float* W2     = (const float*)d_in[10];
    const float* b2     = (const float*)d_in[11];
    const float* g2     = (const float*)d_in[12];
    const float* be2    = (const float*)d_in[13];
    const float* W3     = (const float*)d_in[14];
    const float* b3     = (const float*)d_in[15];
    const long long* e64 = (const long long*)d_in[16];
    const int*       e32 = (const int*)d_in[16];
    const long long* bt64 = (const long long*)d_in[17];
    const int*       bt32 = (const int*)d_in[17];
    float* out = (float*)d_out;

    const int GBLK = (NN + 127) / 128;   // 1563

    k_detect<<<1, 32>>>(e64);
    k_init<<<4, 256>>>();
    k_deginit<<<(NN + 255) / 256, 256>>>();
    k_edgedeg<<<1024, 256>>>(e64, e32);
    k_dinv<<<(NN + 255) / 256, 256>>>();
    k_mma<64, 0><<<GBLK, 256>>>(x, W_gcn, b_gcn);        // xw + self-loop agg
    k_scatter<<<4096, 256>>>(e64, e32);
    k_h0<<<2048, 256>>>(b_gcn);                          // BN0 stats only
    k_fold1<<<1, H>>>(g0, be0, W1, b1);
    k_mma<128, 1><<<GBLK, 256>>>(b_gcn, nullptr, nullptr); // h1 (globals + inline relu)
    k_mma<32, 2><<<GBLK, 256>>>(action, W2, b2);           // h2 -> g_xw
    k_fold3<<<1, H>>>(g1, be1, g2, be2, W3, b3);
    k_z<<<NN / 8, 256>>>(bt64, bt32);
    k_final<<<4, 256>>>(out, b3);
}

// round 9
// speedup vs baseline: 1.5017x; 1.5017x over previous
#include <cuda_runtime.h>
#include <cuda_bf16.h>
#include <math.h>

#define NN 200000
#define NE 1600000
#define NB 1000
#define H  128

// ------------------------- device scratch (no allocs allowed) ----------------
__device__ float  g_xw [(size_t)NN * H];   // xW_gcn, later reused for h2
__device__ float  g_agg[(size_t)NN * H];   // GCN aggregate (pre-bias/relu)
__device__ float  g_h1 [(size_t)NN * H];   // h1
__device__ float  g_deg[NN];               // degree -> dinv (in place)
__device__ double g_stats[6 * H];          // sum0,sq0,sum1,sq1,sum2,sq2
__device__ float  g_W1f[H * H];            // BN0-folded W1
__device__ float  g_b1f[H];
__device__ float  g_W3a[H], g_W3b[H];
__device__ float  g_c;
__device__ float  g_gsum[NB], g_gcnt[NB];
__device__ int    g_is64;
// Pre-split, pre-swizzled bf16 images of the weight matrices (SMEM-verbatim):
// rows = k (K rows x 256B: 128 n as 16 chunks of 16B, chunk c stored at
// c ^ (k&7)). B0: W_gcn (K=64) @0 (16KB); B1: W1f (K=128) @16384 (32KB);
// B2: W2 (K=32) @49152 (8KB).
__device__ __align__(16) unsigned char g_Bh[65536];
__device__ __align__(16) unsigned char g_Bl[65536];

// ------------------------- small helpers -------------------------------------
__device__ __forceinline__ unsigned smem_u32(const void* p) {
    unsigned a;
    asm("{ .reg .u64 t; cvta.to.shared.u64 t, %1; cvt.u32.u64 %0, t; }"
        : "=r"(a) : "l"(p));
    return a;
}
__device__ __forceinline__ void bfsplit2(float a, float b, unsigned& hp, unsigned& lp) {
    __nv_bfloat16 ha = __float2bfloat16_rn(a), hb = __float2bfloat16_rn(b);
    __nv_bfloat16 la = __float2bfloat16_rn(a - __bfloat162float(ha));
    __nv_bfloat16 lb = __float2bfloat16_rn(b - __bfloat162float(hb));
    hp = ((unsigned)__bfloat16_as_ushort(hb) << 16) | (unsigned)__bfloat16_as_ushort(ha);
    lp = ((unsigned)__bfloat16_as_ushort(lb) << 16) | (unsigned)__bfloat16_as_ushort(la);
}

#define LDSM4(r0, r1, r2, r3, a) \
    asm volatile("ldmatrix.sync.aligned.m8n8.x4.shared.b16 {%0,%1,%2,%3}, [%4];" \
                 : "=r"(r0), "=r"(r1), "=r"(r2), "=r"(r3) : "r"(a))
#define LDSM4T(r0, r1, r2, r3, a) \
    asm volatile("ldmatrix.sync.aligned.m8n8.x4.trans.shared.b16 {%0,%1,%2,%3}, [%4];" \
                 : "=r"(r0), "=r"(r1), "=r"(r2), "=r"(r3) : "r"(a))

__device__ __forceinline__ void bmma(float* c, const unsigned* a, const unsigned* b) {
    asm volatile(
        "mma.sync.aligned.m16n8k16.row.col.f32.bf16.bf16.f32 "
        "{%0,%1,%2,%3}, {%4,%5,%6,%7}, {%8,%9}, {%0,%1,%2,%3};"
        : "+f"(c[0]), "+f"(c[1]), "+f"(c[2]), "+f"(c[3])
        : "r"(a[0]), "r"(a[1]), "r"(a[2]), "r"(a[3]), "r"(b[0]), "r"(b[1]));
}

// ------------------------- misc small kernels --------------------------------
__global__ void k_detect(const long long* __restrict__ ei) {
    if (threadIdx.x == 0) {
        int ok = 1;
        for (int i = 0; i < 128; i++) {
            long long v = ei[i];
            if (v < 0 || v >= NN) ok = 0;
        }
        g_is64 = ok;
    }
}
__global__ void k_init() {
    int i = blockIdx.x * blockDim.x + threadIdx.x;
    if (i < 6 * H) g_stats[i] = 0.0;
    if (i < NB) { g_gsum[i] = 0.f; g_gcnt[i] = 0.f; }
}
__global__ void k_deginit() {
    int i = blockIdx.x * blockDim.x + threadIdx.x;
    if (i < NN) g_deg[i] = 1.0f;
}
__global__ void k_edgedeg(const long long* __restrict__ e64,
                          const int* __restrict__ e32) {
    int is64 = g_is64;
    for (int e = blockIdx.x * blockDim.x + threadIdx.x; e < NE;
         e += gridDim.x * blockDim.x) {
        int d = is64 ? (int)e64[NE + e] : e32[NE + e];
        atomicAdd(&g_deg[d], 1.0f);
    }
}
__global__ void k_dinv() {
    int i = blockIdx.x * blockDim.x + threadIdx.x;
    if (i < NN) g_deg[i] = rsqrtf(g_deg[i]);
}

// ------------------------- weight prep: split + pre-swizzle ------------------
// WHICH 0: W_gcn (K=64) @0 ; 1: g_W1f (K=128) @16384 ; 2: W2 (K=32) @49152
template<int WHICH>
__global__ void k_prep(const float* __restrict__ srcp) {
    const int K   = (WHICH == 0) ? 64 : (WHICH == 1) ? 128 : 32;
    const int off = (WHICH == 0) ? 0 : (WHICH == 1) ? 16384 : 49152;
    const float* src = (WHICH == 1) ? (const float*)g_W1f : srcp;
    int idx = blockIdx.x * blockDim.x + threadIdx.x;
    if (idx >= K * 128) return;
    int k = idx >> 7, n = idx & 127;
    float v = src[k * 128 + n];
    __nv_bfloat16 h = __float2bfloat16_rn(v);
    __nv_bfloat16 l = __float2bfloat16_rn(v - __bfloat162float(h));
    unsigned o = (unsigned)(k * 256 + (((n >> 3) ^ (k & 7)) * 16) + (n & 7) * 2);
    *(unsigned short*)(g_Bh + off + o) = __bfloat16_as_ushort(h);
    *(unsigned short*)(g_Bl + off + o) = __bfloat16_as_ushort(l);
}

// ---------------- bf16 mma.sync GEMM: C[128,128] = A[128,K] @ W[K,128] -------
// 256 threads = 8 warps, warp grid 4(m) x 2(n): warp tile 32m x 64n.
// Full-K single-stage SMEM images (hi/lo), XOR-chunk swizzle, ldmatrix feeds,
// 3-pass split bf16 into fp32 register accumulators.
// EPI 0: g_xw = C, g_agg = C * dinv^2.                   (A=x, K=64)
// EPI 1: A = relu(g_agg + abias) on load; g_h1 = relu(C + g_b1f); stats[2],[3].
// EPI 2: g_xw = relu(C + cbias); stats[4],[5].           (A=action, K=32)
template<int K, int EPI>
__global__ void __launch_bounds__(256)
k_bmma(const float* __restrict__ Aext, const float* __restrict__ abias,
       const float* __restrict__ cbias) {
    constexpr int CH    = K / 8;                    // A 16B-chunks per row
    constexpr int AMASK = (CH < 8 ? CH : 8) - 1;    // A swizzle mask
    constexpr int ASZ   = 128 * K * 2;              // bytes per A image
    constexpr int BSZ   = K * 128 * 2;              // bytes per B image
    extern __shared__ __align__(128) unsigned char smem[];
    unsigned char* A_hi = smem;
    unsigned char* A_lo = smem + ASZ;
    unsigned char* B_hi = smem + 2 * ASZ;
    unsigned char* B_lo = smem + 2 * ASZ + BSZ;
    float* s_sum = (float*)(smem + 2 * ASZ + 2 * BSZ);
    float* s_sq  = s_sum + H;

    const int tid   = threadIdx.x;
    const int lane  = tid & 31;
    const int wid   = tid >> 5;
    const int mwarp = wid & 3;          // m block: mwarp*32
    const int nwarp = wid >> 2;         // n block: nwarp*64
    const int bm    = blockIdx.x * 128;
    const float* A  = (EPI == 1) ? (const float*)g_agg : Aext;
    const int boff  = (EPI == 0) ? 0 : (EPI == 1) ? 16384 : 49152;

    if (EPI != 0 && tid < H) { s_sum[tid] = 0.f; s_sq[tid] = 0.f; }

    // ---- copy pre-swizzled B hi/lo (L2-hot) ----
    {
        const uint4* sh = (const uint4*)(g_Bh + boff);
        const uint4* sl = (const uint4*)(g_Bl + boff);
        uint4* dh = (uint4*)B_hi;
        uint4* dl = (uint4*)B_lo;
#pragma unroll
        for (int i = tid; i < BSZ / 16; i += 256) { dh[i] = sh[i]; dl[i] = sl[i]; }
    }

    // ---- load + split-convert A tile (swizzled SMEM image) ----
    {
        const int row0 = tid / CH;               // advances by 256/CH per pass
        const int c    = tid % CH;
        const int kc   = c * 8;
#pragma unroll
        for (int pass = 0; pass < CH / 2; pass++) {
            int m  = row0 + pass * (256 / CH);
            int gr = bm + m;
            float v[8];
            if (gr < NN) {
                float4 x0 = *(const float4*)&A[(size_t)gr * K + kc];
                float4 x1 = *(const float4*)&A[(size_t)gr * K + kc + 4];
                v[0] = x0.x; v[1] = x0.y; v[2] = x0.z; v[3] = x0.w;
                v[4] = x1.x; v[5] = x1.y; v[6] = x1.z; v[7] = x1.w;
                if (EPI == 1) {
                    float4 b0 = *(const float4*)&abias[kc];
                    float4 b1 = *(const float4*)&abias[kc + 4];
                    v[0] = fmaxf(v[0] + b0.x, 0.f); v[1] = fmaxf(v[1] + b0.y, 0.f);
                    v[2] = fmaxf(v[2] + b0.z, 0.f); v[3] = fmaxf(v[3] + b0.w, 0.f);
                    v[4] = fmaxf(v[4] + b1.x, 0.f); v[5] = fmaxf(v[5] + b1.y, 0.f);
                    v[6] = fmaxf(v[6] + b1.z, 0.f); v[7] = fmaxf(v[7] + b1.w, 0.f);
                }
            } else {
#pragma unroll
                for (int j = 0; j < 8; j++) v[j] = 0.f;
            }
            uint4 hp, lp;
            bfsplit2(v[0], v[1], hp.x, lp.x);
            bfsplit2(v[2], v[3], hp.y, lp.y);
            bfsplit2(v[4], v[5], hp.z, lp.z);
            bfsplit2(v[6], v[7], hp.w, lp.w);
            unsigned o = (unsigned)(m * (K * 2) + ((c ^ (m & AMASK)) * 16));
            *(uint4*)(A_hi + o) = hp;
            *(uint4*)(A_lo + o) = lp;
        }
    }
    __syncthreads();

    const unsigned uAh = smem_u32(A_hi), uAl = smem_u32(A_lo);
    const unsigned uBh = smem_u32(B_hi), uBl = smem_u32(B_lo);

    float acc[2][8][4];
#pragma unroll
    for (int i = 0; i < 2; i++)
#pragma unroll
        for (int j = 0; j < 8; j++)
#pragma unroll
            for (int q = 0; q < 4; q++) acc[i][j][q] = 0.f;

    // ---- main loop over k16 steps ----
    for (int k16 = 0; k16 < K / 16; k16++) {
        unsigned ah[2][4], al[2][4];
#pragma unroll
        for (int mf = 0; mf < 2; mf++) {
            int row = mwarp * 32 + mf * 16 + (lane & 15);
            int c   = 2 * k16 + (lane >> 4);
            unsigned o = (unsigned)(row * (K * 2) + ((c ^ (row & AMASK)) * 16));
            LDSM4(ah[mf][0], ah[mf][1], ah[mf][2], ah[mf][3], uAh + o);
            LDSM4(al[mf][0], al[mf][1], al[mf][2], al[mf][3], uAl + o);
        }
        unsigned bh[8][2], bl[8][2];
#pragma unroll
        for (int g = 0; g < 4; g++) {           // n16 groups within warp's 64n
            int row = k16 * 16 + (lane & 15);
            int c   = nwarp * 8 + g * 2 + (lane >> 4);
            unsigned o = (unsigned)(row * 256 + ((c ^ (row & 7)) * 16));
            unsigned r0, r1, r2, r3;
            LDSM4T(r0, r1, r2, r3, uBh + o);
            bh[2 * g][0] = r0; bh[2 * g][1] = r1;
            bh[2 * g + 1][0] = r2; bh[2 * g + 1][1] = r3;
            LDSM4T(r0, r1, r2, r3, uBl + o);
            bl[2 * g][0] = r0; bl[2 * g][1] = r1;
            bl[2 * g + 1][0] = r2; bl[2 * g + 1][1] = r3;
        }
#pragma unroll
        for (int mf = 0; mf < 2; mf++)
#pragma unroll
            for (int nf = 0; nf < 8; nf++) {
                bmma(acc[mf][nf], ah[mf], bh[nf]);
                bmma(acc[mf][nf], ah[mf], bl[nf]);
                bmma(acc[mf][nf], al[mf], bh[nf]);
            }
    }

    // ---- epilogue (accumulators already in registers) ----
    const int qr = lane >> 2;           // 0..7
    const int qc = (lane & 3) * 2;      // 0,2,4,6
    if (EPI == 0) {
#pragma unroll
        for (int mf = 0; mf < 2; mf++) {
            int m1 = bm + mwarp * 32 + mf * 16 + qr;
            int m2 = m1 + 8;
            float d1 = (m1 < NN) ? g_deg[m1] : 0.f; d1 *= d1;
            float d2 = (m2 < NN) ? g_deg[m2] : 0.f; d2 *= d2;
#pragma unroll
            for (int nf = 0; nf < 8; nf++) {
                int n = nwarp * 64 + nf * 8 + qc;
                float* c4 = acc[mf][nf];
                if (m1 < NN) {
                    *(float2*)&g_xw [(size_t)m1 * H + n] = make_float2(c4[0], c4[1]);
                    *(float2*)&g_agg[(size_t)m1 * H + n] =
                        make_float2(c4[0] * d1, c4[1] * d1);
                }
                if (m2 < NN) {
                    *(float2*)&g_xw [(size_t)m2 * H + n] = make_float2(c4[2], c4[3]);
                    *(float2*)&g_agg[(size_t)m2 * H + n] =
                        make_float2(c4[2] * d2, c4[3] * d2);
                }
            }
        }
    } else {
        float* dst = (EPI == 1) ? (float*)g_h1 : (float*)g_xw;
        const float* cb = (EPI == 1) ? (const float*)g_b1f : cbias;
        float fs[8][2], fq[8][2];
#pragma unroll
        for (int nf = 0; nf < 8; nf++) {
            fs[nf][0] = fs[nf][1] = 0.f;
            fq[nf][0] = fq[nf][1] = 0.f;
        }
#pragma unroll
        for (int mf = 0; mf < 2; mf++) {
            int m1 = bm + mwarp * 32 + mf * 16 + qr;
            int m2 = m1 + 8;
#pragma unroll
            for (int nf = 0; nf < 8; nf++) {
                int n = nwarp * 64 + nf * 8 + qc;
                float2 bb = *(const float2*)&cb[n];
                float* c4 = acc[mf][nf];
                float v0 = fmaxf(c4[0] + bb.x, 0.f);
                float v1 = fmaxf(c4[1] + bb.y, 0.f);
                float v2 = fmaxf(c4[2] + bb.x, 0.f);
                float v3 = fmaxf(c4[3] + bb.y, 0.f);
                if (m1 < NN)
                    *(float2*)&dst[(size_t)m1 * H + n] = make_float2(v0, v1);
                else { v0 = 0.f; v1 = 0.f; }
                if (m2 < NN)
                    *(float2*)&dst[(size_t)m2 * H + n] = make_float2(v2, v3);
                else { v2 = 0.f; v3 = 0.f; }
                fs[nf][0] += v0 + v2; fs[nf][1] += v1 + v3;
                fq[nf][0] += v0 * v0 + v2 * v2;
                fq[nf][1] += v1 * v1 + v3 * v3;
            }
        }
#pragma unroll
        for (int off = 4; off <= 16; off <<= 1)
#pragma unroll
            for (int nf = 0; nf < 8; nf++)
#pragma unroll
                for (int j = 0; j < 2; j++) {
                    fs[nf][j] += __shfl_down_sync(0xffffffffu, fs[nf][j], off);
                    fq[nf][j] += __shfl_down_sync(0xffffffffu, fq[nf][j], off);
                }
        if (lane < 4) {
#pragma unroll
            for (int nf = 0; nf < 8; nf++) {
                int n = nwarp * 64 + nf * 8 + lane * 2;
                atomicAdd(&s_sum[n],     fs[nf][0]);
                atomicAdd(&s_sum[n + 1], fs[nf][1]);
                atomicAdd(&s_sq[n],      fq[nf][0]);
                atomicAdd(&s_sq[n + 1],  fq[nf][1]);
            }
        }
        __syncthreads();
        if (tid < H) {
            const int soff = (EPI == 1) ? 2 : 4;
            atomicAdd(&g_stats[(size_t)soff * H + tid], (double)s_sum[tid]);
            atomicAdd(&g_stats[(size_t)(soff + 1) * H + tid], (double)s_sq[tid]);
        }
    }
}

// ------------------------- edge scatter (GCN aggregate) ----------------------
__global__ void k_scatter(const long long* __restrict__ e64,
                          const int* __restrict__ e32) {
    const int is64   = g_is64;
    const int lane   = threadIdx.x & 31;
    const int warp   = (blockIdx.x * blockDim.x + threadIdx.x) >> 5;
    const int nwarps = (gridDim.x * blockDim.x) >> 5;
    for (int e = warp; e < NE; e += nwarps) {
        int s, d;
        if (is64) { s = (int)__ldg(&e64[e]); d = (int)__ldg(&e64[NE + e]); }
        else      { s = __ldg(&e32[e]);      d = __ldg(&e32[NE + e]); }
        float w = g_deg[s] * g_deg[d];
        float4 v = *(const float4*)&g_xw[(size_t)s * H + lane * 4];
        v.x *= w; v.y *= w; v.z *= w; v.w *= w;
        float* p = &g_agg[(size_t)d * H + lane * 4];
        asm volatile("red.global.add.v4.f32 [%0], {%1,%2,%3,%4};"
                     :: "l"(p), "f"(v.x), "f"(v.y), "f"(v.z), "f"(v.w)
                     : "memory");
    }
}

// ---------------- h0 stats only (h1 GEMM recomputes relu(agg+b) on load) -----
__global__ void k_h0(const float* __restrict__ bgcn) {
    const int f  = threadIdx.x & (H - 1);
    const float bv = bgcn[f];
    double s = 0.0, q = 0.0;
    const size_t total  = (size_t)NN * H;
    const size_t stride = (size_t)gridDim.x * blockDim.x;
    for (size_t i = (size_t)blockIdx.x * blockDim.x + threadIdx.x; i < total;
         i += stride) {
        float v = fmaxf(g_agg[i] + bv, 0.f);
        s += v; q += (double)v * v;
    }
    __shared__ double sS[256], sQ[256];
    sS[threadIdx.x] = s; sQ[threadIdx.x] = q;
    __syncthreads();
    if (threadIdx.x < H) {
        double ts = sS[threadIdx.x] + sS[threadIdx.x + H];
        double tq = sQ[threadIdx.x] + sQ[threadIdx.x + H];
        atomicAdd(&g_stats[0 * H + f], ts);
        atomicAdd(&g_stats[1 * H + f], tq);
    }
}

// ------------------------- fold BN0 into W1 ----------------------------------
__global__ void k_fold1(const float* __restrict__ g0, const float* __restrict__ be0,
                        const float* __restrict__ W1, const float* __restrict__ b1) {
    __shared__ float s0[H], t0[H];
    const int f = threadIdx.x;
    double mu  = g_stats[0 * H + f] / (double)NN;
    double var = g_stats[1 * H + f] / (double)NN - mu * mu;
    float  r   = (float)(1.0 / sqrt(var + 1e-5));
    float  sf  = g0[f] * r;
    float  tf  = be0[f] - (float)mu * sf;
    s0[f] = sf; t0[f] = tf;
    __syncthreads();
    float bacc = b1[f];
    for (int k = 0; k < H; k++) {
        float w = W1[k * H + f];
        g_W1f[k * H + f] = s0[k] * w;
        bacc += t0[k] * w;
    }
    g_b1f[f] = bacc;
}

// ------------------------- fold BN1/BN2 + W3 ---------------------------------
__global__ void k_fold3(const float* __restrict__ g1, const float* __restrict__ be1,
                        const float* __restrict__ g2, const float* __restrict__ be2,
                        const float* __restrict__ W3, const float* __restrict__ b3) {
    const int f = threadIdx.x;
    double mu1 = g_stats[2 * H + f] / (double)NN;
    double v1  = g_stats[3 * H + f] / (double)NN - mu1 * mu1;
    float  r1  = (float)(1.0 / sqrt(v1 + 1e-5));
    float  s1  = g1[f] * r1;
    float  t1  = be1[f] - (float)mu1 * s1;
    double mu2 = g_stats[4 * H + f] / (double)NN;
    double v2  = g_stats[5 * H + f] / (double)NN - mu2 * mu2;
    float  r2  = (float)(1.0 / sqrt(v2 + 1e-5));
    float  s2  = g2[f] * r2;
    float  t2  = be2[f] - (float)mu2 * s2;
    float w3a = W3[f], w3b = W3[H + f];
    g_W3a[f] = w3a * s1;
    g_W3b[f] = w3b * s2;
    __shared__ double red[H];
    red[f] = (double)(t1 * w3a) + (double)(t2 * w3b);
    __syncthreads();
    for (int o = 64; o > 0; o >>= 1) {
        if (f < o) red[f] += red[f + o];
        __syncthreads();
    }
    if (f == 0) g_c = (float)red[0] + b3[0];
}

// ------------------------- per-node scalar + segment sum ---------------------
__global__ void k_z(const long long* __restrict__ b64, const int* __restrict__ b32) {
    const int is64 = g_is64;
    const int lane = threadIdx.x & 31;
    const int n    = (blockIdx.x * blockDim.x + threadIdx.x) >> 5;
    if (n >= NN) return;
    float4 a  = *(const float4*)&g_h1[(size_t)n * H + lane * 4];
    float4 b  = *(const float4*)&g_xw[(size_t)n * H + lane * 4];   // h2
    float4 wa = *(const float4*)&g_W3a[lane * 4];
    float4 wb = *(const float4*)&g_W3b[lane * 4];
    float z = a.x * wa.x + a.y * wa.y + a.z * wa.z + a.w * wa.w +
              b.x * wb.x + b.y * wb.y + b.z * wb.z + b.w * wb.w;
#pragma unroll
    for (int o = 16; o > 0; o >>= 1) z += __shfl_xor_sync(0xffffffffu, z, o);
    if (lane == 0) {
        int g = is64 ? (int)b64[n] : b32[n];
        atomicAdd(&g_gsum[g], z);
        atomicAdd(&g_gcnt[g], 1.0f);
    }
}

__global__ void k_final(float* __restrict__ out, const float* __restrict__ b3) {
    int b = blockIdx.x * blockDim.x + threadIdx.x;
    if (b < NB) {
        float c = g_gcnt[b];
        out[b] = (c > 0.f) ? (g_gsum[b] / c + g_c) : b3[0];
    }
}

// ------------------------- launch ---------------------------------------------
extern "C" void kernel_launch(void* const* d_in, const int* in_sizes, int n_in,
                              void* d_out, int out_size) {
    const float* x      = (const float*)d_in[0];
    const float* action = (const float*)d_in[1];
    const float* W_gcn  = (const float*)d_in[2];
    const float* b_gcn  = (const float*)d_in[3];
    const float* g0     = (const float*)d_in[4];
    const float* be0    = (const float*)d_in[5];
    const float* W1     = (const float*)d_in[6];
    const float* b1     = (const float*)d_in[7];
    const float* g1     = (const float*)d_in[8];
    const float* be1    = (const float*)d_in[9];
    const float* W2     = (const float*)d_in[10];
    const float* b2     = (const float*)d_in[11];
    const float* g2     = (const float*)d_in[12];
    const float* be2    = (const float*)d_in[13];
    const float* W3     = (const float*)d_in[14];
    const float* b3     = (const float*)d_in[15];
    const long long* e64 = (const long long*)d_in[16];
    const int*       e32 = (const int*)d_in[16];
    const long long* bt64 = (const long long*)d_in[17];
    const int*       bt32 = (const int*)d_in[17];
    float* out = (float*)d_out;

    const int GBLK = (NN + 127) / 128;   // 1563
    // smem bytes: 2*ASZ + 2*BSZ + 1024
    const int SM64  = 2 * (128 * 64 * 2)  + 2 * (64 * 128 * 2)  + 1024; // 66560
    const int SM128 = 2 * (128 * 128 * 2) + 2 * (128 * 128 * 2) + 1024; // 132096
    const int SM32  = 2 * (128 * 32 * 2)  + 2 * (32 * 128 * 2)  + 1024; // 33792

    cudaFuncSetAttribute(k_bmma<64, 0>,
                         cudaFuncAttributeMaxDynamicSharedMemorySize, SM64);
    cudaFuncSetAttribute(k_bmma<128, 1>,
                         cudaFuncAttributeMaxDynamicSharedMemorySize, SM128);
    cudaFuncSetAttribute(k_bmma<32, 2>,
                         cudaFuncAttributeMaxDynamicSharedMemorySize, SM32);

    k_detect<<<1, 32>>>(e64);
    k_init<<<4, 256>>>();
    k_deginit<<<(NN + 255) / 256, 256>>>();
    k_edgedeg<<<1024, 256>>>(e64, e32);
    k_dinv<<<(NN + 255) / 256, 256>>>();
    k_prep<0><<<32, 256>>>(W_gcn);
    k_prep<2><<<16, 256>>>(W2);
    k_bmma<64, 0><<<GBLK, 256, SM64>>>(x, nullptr, nullptr);       // xw + self-loop
    k_scatter<<<4096, 256>>>(e64, e32);
    k_h0<<<2048, 256>>>(b_gcn);                                    // BN0 stats
    k_fold1<<<1, H>>>(g0, be0, W1, b1);
    k_prep<1><<<64, 256>>>(nullptr);                               // W1f -> bf16
    k_bmma<128, 1><<<GBLK, 256, SM128>>>(nullptr, b_gcn, nullptr); // h1
    k_bmma<32, 2><<<GBLK, 256, SM32>>>(action, nullptr, b2);       // h2 -> g_xw
    k_fold3<<<1, H>>>(g1, be1, g2, be2, W3, b3);
    k_z<<<NN / 8, 256>>>(bt64, bt32);
    k_final<<<4, 256>>>(out, b3);
}

// round 10
// speedup vs baseline: 2.0823x; 1.3866x over previous
#include <cuda_runtime.h>
#include <cuda_bf16.h>
#include <math.h>

#define NN 200000
#define NE 1600000
#define NB 1000
#define H  128
#define NBLK 196          // ceil(NN/1024)

// ------------------------- device scratch (no allocs allowed) ----------------
__device__ float  g_xw [(size_t)NN * H];   // dinv*xW_gcn, later reused for h2
__device__ float  g_agg[(size_t)NN * H];   // h0 = relu(GCN agg + bias)
__device__ float  g_h1 [(size_t)NN * H];   // h1
__device__ float  g_deg[NN];               // dinv
__device__ double g_stats[6 * H];          // sum0,sq0,sum1,sq1,sum2,sq2
__device__ float  g_W1f[H * H];            // BN0-folded W1
__device__ float  g_b1f[H];
__device__ float  g_W3a[H], g_W3b[H];
__device__ float  g_c;
__device__ float  g_gsum[NB], g_gcnt[NB];
__device__ int    g_is64;
// CSR-ish edge structures (counting sort by dst)
__device__ int    g_cnt[NN];               // in-degree (excl self)
__device__ int    g_off[NN];               // exclusive offsets
__device__ int    g_cur[NN];               // running cursors
__device__ int    g_ssrc[NE];              // src ids sorted by dst
__device__ int    g_bsum[256];             // block sums for scan
// Pre-split, pre-swizzled bf16 images of the weight matrices (SMEM-verbatim):
// rows = k (K rows x 256B: 128 n as 16 chunks of 16B, chunk c stored at
// c ^ (k&7)). B0: W_gcn (K=64) @0; B1: W1f (K=128) @16384; B2: W2 (K=32) @49152.
__device__ __align__(16) unsigned char g_Bh[65536];
__device__ __align__(16) unsigned char g_Bl[65536];

// ------------------------- small helpers -------------------------------------
__device__ __forceinline__ unsigned smem_u32(const void* p) {
    unsigned a;
    asm("{ .reg .u64 t; cvta.to.shared.u64 t, %1; cvt.u32.u64 %0, t; }"
        : "=r"(a) : "l"(p));
    return a;
}
__device__ __forceinline__ void bfsplit2(float a, float b, unsigned& hp, unsigned& lp) {
    __nv_bfloat16 ha = __float2bfloat16_rn(a), hb = __float2bfloat16_rn(b);
    __nv_bfloat16 la = __float2bfloat16_rn(a - __bfloat162float(ha));
    __nv_bfloat16 lb = __float2bfloat16_rn(b - __bfloat162float(hb));
    hp = ((unsigned)__bfloat16_as_ushort(hb) << 16) | (unsigned)__bfloat16_as_ushort(ha);
    lp = ((unsigned)__bfloat16_as_ushort(lb) << 16) | (unsigned)__bfloat16_as_ushort(la);
}

#define LDSM4(r0, r1, r2, r3, a) \
    asm volatile("ldmatrix.sync.aligned.m8n8.x4.shared.b16 {%0,%1,%2,%3}, [%4];" \
                 : "=r"(r0), "=r"(r1), "=r"(r2), "=r"(r3) : "r"(a))
#define LDSM4T(r0, r1, r2, r3, a) \
    asm volatile("ldmatrix.sync.aligned.m8n8.x4.trans.shared.b16 {%0,%1,%2,%3}, [%4];" \
                 : "=r"(r0), "=r"(r1), "=r"(r2), "=r"(r3) : "r"(a))

__device__ __forceinline__ void bmma(float* c, const unsigned* a, const unsigned* b) {
    asm volatile(
        "mma.sync.aligned.m16n8k16.row.col.f32.bf16.bf16.f32 "
        "{%0,%1,%2,%3}, {%4,%5,%6,%7}, {%8,%9}, {%0,%1,%2,%3};"
        : "+f"(c[0]), "+f"(c[1]), "+f"(c[2]), "+f"(c[3])
        : "r"(a[0]), "r"(a[1]), "r"(a[2]), "r"(a[3]), "r"(b[0]), "r"(b[1]));
}

// ------------------------- misc small kernels --------------------------------
__global__ void k_detect(const long long* __restrict__ ei) {
    if (threadIdx.x == 0) {
        int ok = 1;
        for (int i = 0; i < 128; i++) {
            long long v = ei[i];
            if (v < 0 || v >= NN) ok = 0;
        }
        g_is64 = ok;
    }
}
__global__ void k_init() {
    int i = blockIdx.x * blockDim.x + threadIdx.x;
    if (i < NN) g_cnt[i] = 0;
    if (i < 6 * H) g_stats[i] = 0.0;
    if (i < NB) { g_gsum[i] = 0.f; g_gcnt[i] = 0.f; }
}
__global__ void k_hist(const long long* __restrict__ e64,
                       const int* __restrict__ e32) {
    int is64 = g_is64;
    for (int e = blockIdx.x * blockDim.x + threadIdx.x; e < NE;
         e += gridDim.x * blockDim.x) {
        int d = is64 ? (int)e64[NE + e] : e32[NE + e];
        atomicAdd(&g_cnt[d], 1);
    }
}
// scan step 1: per-1024-chunk sums
__global__ void k_scan1() {
    __shared__ int sh[256];
    int blk = blockIdx.x, tid = threadIdx.x;
    int s = 0;
#pragma unroll
    for (int k = 0; k < 4; k++) {
        int i = blk * 1024 + tid + k * 256;
        if (i < NN) s += g_cnt[i];
    }
    sh[tid] = s; __syncthreads();
    for (int o = 128; o > 0; o >>= 1) {
        if (tid < o) sh[tid] += sh[tid + o];
        __syncthreads();
    }
    if (tid == 0) g_bsum[blk] = sh[0];
}
// scan step 2: exclusive scan of block sums (single block)
__global__ void k_scan2() {
    __shared__ int sh[256];
    int t = threadIdx.x;
    int v = (t < NBLK) ? g_bsum[t] : 0;
    sh[t] = v; __syncthreads();
    for (int o = 1; o < 256; o <<= 1) {
        int a = (t >= o) ? sh[t - o] : 0;
        __syncthreads();
        sh[t] += a;
        __syncthreads();
    }
    if (t < NBLK) g_bsum[t] = sh[t] - v;
}
// scan step 3: per-element exclusive offsets + cursors + dinv
__global__ void k_scan3() {
    __shared__ int tsum[256];
    int blk = blockIdx.x, tid = threadIdx.x;
    int i0 = blk * 1024 + tid * 4;
    int v[4];
#pragma unroll
    for (int j = 0; j < 4; j++) v[j] = (i0 + j < NN) ? g_cnt[i0 + j] : 0;
    int s = v[0] + v[1] + v[2] + v[3];
    tsum[tid] = s; __syncthreads();
    for (int o = 1; o < 256; o <<= 1) {
        int a = (tid >= o) ? tsum[tid - o] : 0;
        __syncthreads();
        tsum[tid] += a;
        __syncthreads();
    }
    int off = g_bsum[blk] + tsum[tid] - s;
#pragma unroll
    for (int j = 0; j < 4; j++) {
        int i = i0 + j;
        if (i < NN) {
            g_off[i] = off;
            g_cur[i] = off;
            g_deg[i] = rsqrtf((float)v[j] + 1.0f);   // dinv (deg incl self-loop)
            off += v[j];
        }
    }
}
__global__ void k_sortedges(const long long* __restrict__ e64,
                            const int* __restrict__ e32) {
    int is64 = g_is64;
    for (int e = blockIdx.x * blockDim.x + threadIdx.x; e < NE;
         e += gridDim.x * blockDim.x) {
        int s, d;
        if (is64) { s = (int)e64[e]; d = (int)e64[NE + e]; }
        else      { s = e32[e];      d = e32[NE + e]; }
        int pos = atomicAdd(&g_cur[d], 1);
        g_ssrc[pos] = s;
    }
}

// ------------------------- weight prep: split + pre-swizzle ------------------
template<int WHICH>
__global__ void k_prep(const float* __restrict__ srcp) {
    const int K   = (WHICH == 0) ? 64 : (WHICH == 1) ? 128 : 32;
    const int off = (WHICH == 0) ? 0 : (WHICH == 1) ? 16384 : 49152;
    const float* src = (WHICH == 1) ? (const float*)g_W1f : srcp;
    int idx = blockIdx.x * blockDim.x + threadIdx.x;
    if (idx >= K * 128) return;
    int k = idx >> 7, n = idx & 127;
    float v = src[k * 128 + n];
    __nv_bfloat16 h = __float2bfloat16_rn(v);
    __nv_bfloat16 l = __float2bfloat16_rn(v - __bfloat162float(h));
    unsigned o = (unsigned)(k * 256 + (((n >> 3) ^ (k & 7)) * 16) + (n & 7) * 2);
    *(unsigned short*)(g_Bh + off + o) = __bfloat16_as_ushort(h);
    *(unsigned short*)(g_Bl + off + o) = __bfloat16_as_ushort(l);
}

// ---------------- bf16 mma.sync GEMM: C[128,128] = A[128,K] @ W[K,128] -------
// EPI 0: g_xw = C * dinv (pre-scaled xw').                (A=x, K=64)
// EPI 1: A = g_agg (h0, already relu'd); g_h1 = relu(C + g_b1f); stats[2],[3].
// EPI 2: g_xw = relu(C + cbias); stats[4],[5].            (A=action, K=32)
template<int K, int EPI>
__global__ void __launch_bounds__(256)
k_bmma(const float* __restrict__ Aext, const float* __restrict__ cbias) {
    constexpr int CH    = K / 8;
    constexpr int AMASK = (CH < 8 ? CH : 8) - 1;
    constexpr int ASZ   = 128 * K * 2;
    constexpr int BSZ   = K * 128 * 2;
    extern __shared__ __align__(128) unsigned char smem[];
    unsigned char* A_hi = smem;
    unsigned char* A_lo = smem + ASZ;
    unsigned char* B_hi = smem + 2 * ASZ;
    unsigned char* B_lo = smem + 2 * ASZ + BSZ;
    float* s_sum = (float*)(smem + 2 * ASZ + 2 * BSZ);
    float* s_sq  = s_sum + H;

    const int tid   = threadIdx.x;
    const int lane  = tid & 31;
    const int wid   = tid >> 5;
    const int mwarp = wid & 3;
    const int nwarp = wid >> 2;
    const int bm    = blockIdx.x * 128;
    const float* A  = (EPI == 1) ? (const float*)g_agg : Aext;
    const int boff  = (EPI == 0) ? 0 : (EPI == 1) ? 16384 : 49152;

    if (EPI != 0 && tid < H) { s_sum[tid] = 0.f; s_sq[tid] = 0.f; }

    {   // copy pre-swizzled B hi/lo (L2-hot)
        const uint4* sh = (const uint4*)(g_Bh + boff);
        const uint4* sl = (const uint4*)(g_Bl + boff);
        uint4* dh = (uint4*)B_hi;
        uint4* dl = (uint4*)B_lo;
#pragma unroll
        for (int i = tid; i < BSZ / 16; i += 256) { dh[i] = sh[i]; dl[i] = sl[i]; }
    }

    {   // load + split-convert A tile
        const int row0 = tid / CH;
        const int c    = tid % CH;
        const int kc   = c * 8;
#pragma unroll
        for (int pass = 0; pass < CH / 2; pass++) {
            int m  = row0 + pass * (256 / CH);
            int gr = bm + m;
            float v[8];
            if (gr < NN) {
                float4 x0 = *(const float4*)&A[(size_t)gr * K + kc];
                float4 x1 = *(const float4*)&A[(size_t)gr * K + kc + 4];
                v[0] = x0.x; v[1] = x0.y; v[2] = x0.z; v[3] = x0.w;
                v[4] = x1.x; v[5] = x1.y; v[6] = x1.z; v[7] = x1.w;
            } else {
#pragma unroll
                for (int j = 0; j < 8; j++) v[j] = 0.f;
            }
            uint4 hp, lp;
            bfsplit2(v[0], v[1], hp.x, lp.x);
            bfsplit2(v[2], v[3], hp.y, lp.y);
            bfsplit2(v[4], v[5], hp.z, lp.z);
            bfsplit2(v[6], v[7], hp.w, lp.w);
            unsigned o = (unsigned)(m * (K * 2) + ((c ^ (m & AMASK)) * 16));
            *(uint4*)(A_hi + o) = hp;
            *(uint4*)(A_lo + o) = lp;
        }
    }
    __syncthreads();

    const unsigned uAh = smem_u32(A_hi), uAl = smem_u32(A_lo);
    const unsigned uBh = smem_u32(B_hi), uBl = smem_u32(B_lo);

    float acc[2][8][4];
#pragma unroll
    for (int i = 0; i < 2; i++)
#pragma unroll
        for (int j = 0; j < 8; j++)
#pragma unroll
            for (int q = 0; q < 4; q++) acc[i][j][q] = 0.f;

    for (int k16 = 0; k16 < K / 16; k16++) {
        unsigned ah[2][4], al[2][4];
#pragma unroll
        for (int mf = 0; mf < 2; mf++) {
            int row = mwarp * 32 + mf * 16 + (lane & 15);
            int c   = 2 * k16 + (lane >> 4);
            unsigned o = (unsigned)(row * (K * 2) + ((c ^ (row & AMASK)) * 16));
            LDSM4(ah[mf][0], ah[mf][1], ah[mf][2], ah[mf][3], uAh + o);
            LDSM4(al[mf][0], al[mf][1], al[mf][2], al[mf][3], uAl + o);
        }
        unsigned bh[8][2], bl[8][2];
#pragma unroll
        for (int g = 0; g < 4; g++) {
            int row = k16 * 16 + (lane & 15);
            int c   = nwarp * 8 + g * 2 + (lane >> 4);
            unsigned o = (unsigned)(row * 256 + ((c ^ (row & 7)) * 16));
            unsigned r0, r1, r2, r3;
            LDSM4T(r0, r1, r2, r3, uBh + o);
            bh[2 * g][0] = r0; bh[2 * g][1] = r1;
            bh[2 * g + 1][0] = r2; bh[2 * g + 1][1] = r3;
            LDSM4T(r0, r1, r2, r3, uBl + o);
            bl[2 * g][0] = r0; bl[2 * g][1] = r1;
            bl[2 * g + 1][0] = r2; bl[2 * g + 1][1] = r3;
        }
#pragma unroll
        for (int mf = 0; mf < 2; mf++)
#pragma unroll
            for (int nf = 0; nf < 8; nf++) {
                bmma(acc[mf][nf], ah[mf], bh[nf]);
                bmma(acc[mf][nf], ah[mf], bl[nf]);
                bmma(acc[mf][nf], al[mf], bh[nf]);
            }
    }

    const int qr = lane >> 2;
    const int qc = (lane & 3) * 2;
    if (EPI == 0) {
#pragma unroll
        for (int mf = 0; mf < 2; mf++) {
            int m1 = bm + mwarp * 32 + mf * 16 + qr;
            int m2 = m1 + 8;
            float d1 = (m1 < NN) ? g_deg[m1] : 0.f;   // dinv
            float d2 = (m2 < NN) ? g_deg[m2] : 0.f;
#pragma unroll
            for (int nf = 0; nf < 8; nf++) {
                int n = nwarp * 64 + nf * 8 + qc;
                float* c4 = acc[mf][nf];
                if (m1 < NN)
                    *(float2*)&g_xw[(size_t)m1 * H + n] =
                        make_float2(c4[0] * d1, c4[1] * d1);
                if (m2 < NN)
                    *(float2*)&g_xw[(size_t)m2 * H + n] =
                        make_float2(c4[2] * d2, c4[3] * d2);
            }
        }
    } else {
        float* dst = (EPI == 1) ? (float*)g_h1 : (float*)g_xw;
        const float* cb = (EPI == 1) ? (const float*)g_b1f : cbias;
        float fs[8][2], fq[8][2];
#pragma unroll
        for (int nf = 0; nf < 8; nf++) {
            fs[nf][0] = fs[nf][1] = 0.f;
            fq[nf][0] = fq[nf][1] = 0.f;
        }
#pragma unroll
        for (int mf = 0; mf < 2; mf++) {
            int m1 = bm + mwarp * 32 + mf * 16 + qr;
            int m2 = m1 + 8;
#pragma unroll
            for (int nf = 0; nf < 8; nf++) {
                int n = nwarp * 64 + nf * 8 + qc;
                float2 bb = *(const float2*)&cb[n];
                float* c4 = acc[mf][nf];
                float v0 = fmaxf(c4[0] + bb.x, 0.f);
                float v1 = fmaxf(c4[1] + bb.y, 0.f);
                float v2 = fmaxf(c4[2] + bb.x, 0.f);
                float v3 = fmaxf(c4[3] + bb.y, 0.f);
                if (m1 < NN)
                    *(float2*)&dst[(size_t)m1 * H + n] = make_float2(v0, v1);
                else { v0 = 0.f; v1 = 0.f; }
                if (m2 < NN)
                    *(float2*)&dst[(size_t)m2 * H + n] = make_float2(v2, v3);
                else { v2 = 0.f; v3 = 0.f; }
                fs[nf][0] += v0 + v2; fs[nf][1] += v1 + v3;
                fq[nf][0] += v0 * v0 + v2 * v2;
                fq[nf][1] += v1 * v1 + v3 * v3;
            }
        }
#pragma unroll
        for (int off = 4; off <= 16; off <<= 1)
#pragma unroll
            for (int nf = 0; nf < 8; nf++)
#pragma unroll
                for (int j = 0; j < 2; j++) {
                    fs[nf][j] += __shfl_down_sync(0xffffffffu, fs[nf][j], off);
                    fq[nf][j] += __shfl_down_sync(0xffffffffu, fq[nf][j], off);
                }
        if (lane < 4) {
#pragma unroll
            for (int nf = 0; nf < 8; nf++) {
                int n = nwarp * 64 + nf * 8 + lane * 2;
                atomicAdd(&s_sum[n],     fs[nf][0]);
                atomicAdd(&s_sum[n + 1], fs[nf][1]);
                atomicAdd(&s_sq[n],      fq[nf][0]);
                atomicAdd(&s_sq[n + 1],  fq[nf][1]);
            }
        }
        __syncthreads();
        if (tid < H) {
            const int soff = (EPI == 1) ? 2 : 4;
            atomicAdd(&g_stats[(size_t)soff * H + tid], (double)s_sum[tid]);
            atomicAdd(&g_stats[(size_t)(soff + 1) * H + tid], (double)s_sq[tid]);
        }
    }
}

// ---------------- pull-mode GCN aggregate + h0 + BN0 stats -------------------
// One warp per node: acc = xw'[node] + sum over sorted in-neighbors xw'[s];
// h0 = relu(dinv[d]*acc + bias); write g_agg; accumulate BN0 stats.
__global__ void __launch_bounds__(256) k_gather(const float* __restrict__ bgcn) {
    __shared__ float s_sum[H], s_sq[H];
    const int tid = threadIdx.x, lane = tid & 31, wid = tid >> 5;
    if (tid < H) { s_sum[tid] = 0.f; s_sq[tid] = 0.f; }
    __syncthreads();

    const float4 b4 = *(const float4*)&bgcn[lane * 4];
    float fs[4] = {0, 0, 0, 0}, fq[4] = {0, 0, 0, 0};
    const int step = gridDim.x * 8;

    for (int node = blockIdx.x * 8 + wid; node < NN; node += step) {
        float4 acc = *(const float4*)&g_xw[(size_t)node * H + lane * 4];
        const int base = g_off[node];
        const int cnt  = g_cnt[node];
        for (int c0 = 0; c0 < cnt; c0 += 32) {
            int n = min(cnt - c0, 32);
            int idx = (lane < n) ? g_ssrc[base + c0 + lane] : 0;
            int sc = __shfl_sync(0xffffffffu, idx, 0);
            float4 v = *(const float4*)&g_xw[(size_t)sc * H + lane * 4];
            for (int i = 0; i < n; i++) {
                float4 cur = v;
                if (i + 1 < n) {
                    int sn = __shfl_sync(0xffffffffu, idx, i + 1);
                    v = *(const float4*)&g_xw[(size_t)sn * H + lane * 4];
                }
                acc.x += cur.x; acc.y += cur.y; acc.z += cur.z; acc.w += cur.w;
            }
        }
        const float dv = g_deg[node];
        float h0x = fmaxf(acc.x * dv + b4.x, 0.f);
        float h0y = fmaxf(acc.y * dv + b4.y, 0.f);
        float h0z = fmaxf(acc.z * dv + b4.z, 0.f);
        float h0w = fmaxf(acc.w * dv + b4.w, 0.f);
        *(float4*)&g_agg[(size_t)node * H + lane * 4] =
            make_float4(h0x, h0y, h0z, h0w);
        fs[0] += h0x; fs[1] += h0y; fs[2] += h0z; fs[3] += h0w;
        fq[0] += h0x * h0x; fq[1] += h0y * h0y;
        fq[2] += h0z * h0z; fq[3] += h0w * h0w;
    }

#pragma unroll
    for (int j = 0; j < 4; j++) {
        atomicAdd(&s_sum[lane * 4 + j], fs[j]);
        atomicAdd(&s_sq[lane * 4 + j], fq[j]);
    }
    __syncthreads();
    if (tid < H) {
        atomicAdd(&g_stats[0 * H + tid], (double)s_sum[tid]);
        atomicAdd(&g_stats[1 * H + tid], (double)s_sq[tid]);
    }
}

// ------------------------- fold BN0 into W1 ----------------------------------
__global__ void k_fold1(const float* __restrict__ g0, const float* __restrict__ be0,
                        const float* __restrict__ W1, const float* __restrict__ b1) {
    __shared__ float s0[H], t0[H];
    const int f = threadIdx.x;
    double mu  = g_stats[0 * H + f] / (double)NN;
    double var = g_stats[1 * H + f] / (double)NN - mu * mu;
    float  r   = (float)(1.0 / sqrt(var + 1e-5));
    float  sf  = g0[f] * r;
    float  tf  = be0[f] - (float)mu * sf;
    s0[f] = sf; t0[f] = tf;
    __syncthreads();
    float bacc = b1[f];
    for (int k = 0; k < H; k++) {
        float w = W1[k * H + f];
        g_W1f[k * H + f] = s0[k] * w;
        bacc += t0[k] * w;
    }
    g_b1f[f] = bacc;
}

// ------------------------- fold BN1/BN2 + W3 ---------------------------------
__global__ void k_fold3(const float* __restrict__ g1, const float* __restrict__ be1,
                        const float* __restrict__ g2, const float* __restrict__ be2,
                        const float* __restrict__ W3, const float* __restrict__ b3) {
    const int f = threadIdx.x;
    double mu1 = g_stats[2 * H + f] / (double)NN;
    double v1  = g_stats[3 * H + f] / (double)NN - mu1 * mu1;
    float  r1  = (float)(1.0 / sqrt(v1 + 1e-5));
    float  s1  = g1[f] * r1;
    float  t1  = be1[f] - (float)mu1 * s1;
    double mu2 = g_stats[4 * H + f] / (double)NN;
    double v2  = g_stats[5 * H + f] / (double)NN - mu2 * mu2;
    float  r2  = (float)(1.0 / sqrt(v2 + 1e-5));
    float  s2  = g2[f] * r2;
    float  t2  = be2[f] - (float)mu2 * s2;
    float w3a = W3[f], w3b = W3[H + f];
    g_W3a[f] = w3a * s1;
    g_W3b[f] = w3b * s2;
    __shared__ double red[H];
    red[f] = (double)(t1 * w3a) + (double)(t2 * w3b);
    __syncthreads();
    for (int o = 64; o > 0; o >>= 1) {
        if (f < o) red[f] += red[f + o];
        __syncthreads();
    }
    if (f == 0) g_c = (float)red[0] + b3[0];
}

// ------------------------- per-node scalar + segment sum ---------------------
__global__ void k_z(const long long* __restrict__ b64, const int* __restrict__ b32) {
    const int is64 = g_is64;
    const int lane = threadIdx.x & 31;
    const int n    = (blockIdx.x * blockDim.x + threadIdx.x) >> 5;
    if (n >= NN) return;
    float4 a  = *(const float4*)&g_h1[(size_t)n * H + lane * 4];
    float4 b  = *(const float4*)&g_xw[(size_t)n * H + lane * 4];   // h2
    float4 wa = *(const float4*)&g_W3a[lane * 4];
    float4 wb = *(const float4*)&g_W3b[lane * 4];
    float z = a.x * wa.x + a.y * wa.y + a.z * wa.z + a.w * wa.w +
              b.x * wb.x + b.y * wb.y + b.z * wb.z + b.w * wb.w;
#pragma unroll
    for (int o = 16; o > 0; o >>= 1) z += __shfl_xor_sync(0xffffffffu, z, o);
    if (lane == 0) {
        int g = is64 ? (int)b64[n] : b32[n];
        atomicAdd(&g_gsum[g], z);
        atomicAdd(&g_gcnt[g], 1.0f);
    }
}

__global__ void k_final(float* __restrict__ out, const float* __restrict__ b3) {
    int b = blockIdx.x * blockDim.x + threadIdx.x;
    if (b < NB) {
        float c = g_gcnt[b];
        out[b] = (c > 0.f) ? (g_gsum[b] / c + g_c) : b3[0];
    }
}

// ------------------------- launch ---------------------------------------------
extern "C" void kernel_launch(void* const* d_in, const int* in_sizes, int n_in,
                              void* d_out, int out_size) {
    const float* x      = (const float*)d_in[0];
    const float* action = (const float*)d_in[1];
    const float* W_gcn  = (const float*)d_in[2];
    const float* b_gcn  = (const float*)d_in[3];
    const float* g0     = (const float*)d_in[4];
    const float* be0    = (const float*)d_in[5];
    const float* W1     = (const float*)d_in[6];
    const float* b1     = (const float*)d_in[7];
    const float* g1     = (const float*)d_in[8];
    const float* be1    = (const float*)d_in[9];
    const float* W2     = (const float*)d_in[10];
    const float* b2     = (const float*)d_in[11];
    const float* g2     = (const float*)d_in[12];
    const float* be2    = (const float*)d_in[13];
    const float* W3     = (const float*)d_in[14];
    const float* b3     = (const float*)d_in[15];
    const long long* e64 = (const long long*)d_in[16];
    const int*       e32 = (const int*)d_in[16];
    const long long* bt64 = (const long long*)d_in[17];
    const int*       bt32 = (const int*)d_in[17];
    float* out = (float*)d_out;

    const int GBLK = (NN + 127) / 128;   // 1563
    const int SM64  = 2 * (128 * 64 * 2)  + 2 * (64 * 128 * 2)  + 1024; // 66560
    const int SM128 = 2 * (128 * 128 * 2) + 2 * (128 * 128 * 2) + 1024; // 132096
    const int SM32  = 2 * (128 * 32 * 2)  + 2 * (32 * 128 * 2)  + 1024; // 33792

    cudaFuncSetAttribute(k_bmma<64, 0>,
                         cudaFuncAttributeMaxDynamicSharedMemorySize, SM64);
    cudaFuncSetAttribute(k_bmma<128, 1>,
                         cudaFuncAttributeMaxDynamicSharedMemorySize, SM128);
    cudaFuncSetAttribute(k_bmma<32, 2>,
                         cudaFuncAttributeMaxDynamicSharedMemorySize, SM32);

    k_detect<<<1, 32>>>(e64);
    k_init<<<(NN + 255) / 256, 256>>>();
    k_hist<<<1024, 256>>>(e64, e32);
    k_scan1<<<NBLK, 256>>>();
    k_scan2<<<1, 256>>>();
    k_scan3<<<NBLK, 256>>>();
    k_sortedges<<<1024, 256>>>(e64, e32);
    k_prep<0><<<32, 256>>>(W_gcn);
    k_prep<2><<<16, 256>>>(W2);
    k_bmma<64, 0><<<GBLK, 256, SM64>>>(x, nullptr);         // xw' = dinv * xW
    k_gather<<<1536, 256>>>(b_gcn);                         // h0 + BN0 stats
    k_fold1<<<1, H>>>(g0, be0, W1, b1);
    k_prep<1><<<64, 256>>>(nullptr);                        // W1f -> bf16
    k_bmma<128, 1><<<GBLK, 256, SM128>>>(nullptr, nullptr); // h1
    k_bmma<32, 2><<<GBLK, 256, SM32>>>(action, b2);         // h2 -> g_xw
    k_fold3<<<1, H>>>(g1, be1, g2, be2, W3, b3);
    k_z<<<NN / 8, 256>>>(bt64, bt32);
    k_final<<<4, 256>>>(out, b3);
}

// round 11
// speedup vs baseline: 2.2973x; 1.1032x over previous
#include <cuda_runtime.h>
#include <cuda_fp16.h>
#include <math.h>

#define NN 200000
#define NE 1600000
#define NB 1000
#define H  128
#define NBLK 196          // ceil(NN/1024)

// ------------------------- device scratch (no allocs allowed) ----------------
__device__ float  g_xw [(size_t)NN * H];   // dinv*xW_gcn, later reused for h2
__device__ float  g_agg[(size_t)NN * H];   // h0 = relu(GCN agg + bias)
__device__ float  g_h1 [(size_t)NN * H];   // h1
__device__ float  g_deg[NN];               // dinv
__device__ double g_stats[6 * H];          // sum0,sq0,sum1,sq1,sum2,sq2
__device__ float  g_W1f[H * H];            // BN0-folded W1
__device__ float  g_b1f[H];
__device__ float  g_W3a[H], g_W3b[H];
__device__ float  g_c;
__device__ float  g_gsum[NB], g_gcnt[NB];
__device__ int    g_is64;
// CSR-ish edge structures (counting sort by dst)
__device__ int    g_cnt[NN];               // in-degree (excl self)
__device__ int    g_off[NN];               // exclusive offsets
__device__ int    g_cur[NN];               // running cursors
__device__ int    g_ssrc[NE];              // src ids sorted by dst
__device__ int    g_bsum[256];             // block sums for scan
// Pre-split, pre-swizzled fp16 hi/lo images of the weight matrices
// (SMEM-verbatim): rows = k (K rows x 256B: 128 n as 16 chunks of 16B,
// chunk c stored at c ^ (k&7)).
// B0: W_gcn (K=64) @0; B1: W1f (K=128) @16384; B2: W2 (K=32) @49152.
__device__ __align__(16) unsigned char g_Bh[65536];
__device__ __align__(16) unsigned char g_Bl[65536];

// ------------------------- small helpers -------------------------------------
__device__ __forceinline__ unsigned smem_u32(const void* p) {
    unsigned a;
    asm("{ .reg .u64 t; cvta.to.shared.u64 t, %1; cvt.u32.u64 %0, t; }"
        : "=r"(a) : "l"(p));
    return a;
}
__device__ __forceinline__ unsigned h2pack(float a, float b) {
    __half2 h = __floats2half2_rn(a, b);
    return *(unsigned*)&h;
}

#define LDSM4(r0, r1, r2, r3, a) \
    asm volatile("ldmatrix.sync.aligned.m8n8.x4.shared.b16 {%0,%1,%2,%3}, [%4];" \
                 : "=r"(r0), "=r"(r1), "=r"(r2), "=r"(r3) : "r"(a))
#define LDSM4T(r0, r1, r2, r3, a) \
    asm volatile("ldmatrix.sync.aligned.m8n8.x4.trans.shared.b16 {%0,%1,%2,%3}, [%4];" \
                 : "=r"(r0), "=r"(r1), "=r"(r2), "=r"(r3) : "r"(a))

__device__ __forceinline__ void hmma(float* c, const unsigned* a, const unsigned* b) {
    asm volatile(
        "mma.sync.aligned.m16n8k16.row.col.f32.f16.f16.f32 "
        "{%0,%1,%2,%3}, {%4,%5,%6,%7}, {%8,%9}, {%0,%1,%2,%3};"
        : "+f"(c[0]), "+f"(c[1]), "+f"(c[2]), "+f"(c[3])
        : "r"(a[0]), "r"(a[1]), "r"(a[2]), "r"(a[3]), "r"(b[0]), "r"(b[1]));
}

// ------------------------- misc small kernels --------------------------------
__global__ void k_detect(const long long* __restrict__ ei) {
    if (threadIdx.x == 0) {
        int ok = 1;
        for (int i = 0; i < 128; i++) {
            long long v = ei[i];
            if (v < 0 || v >= NN) ok = 0;
        }
        g_is64 = ok;
    }
}
__global__ void k_init() {
    int i = blockIdx.x * blockDim.x + threadIdx.x;
    if (i < NN) g_cnt[i] = 0;
    if (i < 6 * H) g_stats[i] = 0.0;
    if (i < NB) { g_gsum[i] = 0.f; g_gcnt[i] = 0.f; }
}
__global__ void k_hist(const long long* __restrict__ e64,
                       const int* __restrict__ e32) {
    int is64 = g_is64;
    for (int e = blockIdx.x * blockDim.x + threadIdx.x; e < NE;
         e += gridDim.x * blockDim.x) {
        int d = is64 ? (int)e64[NE + e] : e32[NE + e];
        atomicAdd(&g_cnt[d], 1);
    }
}
__global__ void k_scan1() {
    __shared__ int sh[256];
    int blk = blockIdx.x, tid = threadIdx.x;
    int s = 0;
#pragma unroll
    for (int k = 0; k < 4; k++) {
        int i = blk * 1024 + tid + k * 256;
        if (i < NN) s += g_cnt[i];
    }
    sh[tid] = s; __syncthreads();
    for (int o = 128; o > 0; o >>= 1) {
        if (tid < o) sh[tid] += sh[tid + o];
        __syncthreads();
    }
    if (tid == 0) g_bsum[blk] = sh[0];
}
__global__ void k_scan2() {
    __shared__ int sh[256];
    int t = threadIdx.x;
    int v = (t < NBLK) ? g_bsum[t] : 0;
    sh[t] = v; __syncthreads();
    for (int o = 1; o < 256; o <<= 1) {
        int a = (t >= o) ? sh[t - o] : 0;
        __syncthreads();
        sh[t] += a;
        __syncthreads();
    }
    if (t < NBLK) g_bsum[t] = sh[t] - v;
}
__global__ void k_scan3() {
    __shared__ int tsum[256];
    int blk = blockIdx.x, tid = threadIdx.x;
    int i0 = blk * 1024 + tid * 4;
    int v[4];
#pragma unroll
    for (int j = 0; j < 4; j++) v[j] = (i0 + j < NN) ? g_cnt[i0 + j] : 0;
    int s = v[0] + v[1] + v[2] + v[3];
    tsum[tid] = s; __syncthreads();
    for (int o = 1; o < 256; o <<= 1) {
        int a = (tid >= o) ? tsum[tid - o] : 0;
        __syncthreads();
        tsum[tid] += a;
        __syncthreads();
    }
    int off = g_bsum[blk] + tsum[tid] - s;
#pragma unroll
    for (int j = 0; j < 4; j++) {
        int i = i0 + j;
        if (i < NN) {
            g_off[i] = off;
            g_cur[i] = off;
            g_deg[i] = rsqrtf((float)v[j] + 1.0f);   // dinv (deg incl self-loop)
            off += v[j];
        }
    }
}
__global__ void k_sortedges(const long long* __restrict__ e64,
                            const int* __restrict__ e32) {
    int is64 = g_is64;
    for (int e = blockIdx.x * blockDim.x + threadIdx.x; e < NE;
         e += gridDim.x * blockDim.x) {
        int s, d;
        if (is64) { s = (int)e64[e]; d = (int)e64[NE + e]; }
        else      { s = e32[e];      d = e32[NE + e]; }
        int pos = atomicAdd(&g_cur[d], 1);
        g_ssrc[pos] = s;
    }
}

// ------------------------- weight prep: fp16 split + pre-swizzle -------------
template<int WHICH>
__global__ void k_prep(const float* __restrict__ srcp) {
    const int K   = (WHICH == 0) ? 64 : (WHICH == 1) ? 128 : 32;
    const int off = (WHICH == 0) ? 0 : (WHICH == 1) ? 16384 : 49152;
    const float* src = (WHICH == 1) ? (const float*)g_W1f : srcp;
    int idx = blockIdx.x * blockDim.x + threadIdx.x;
    if (idx >= K * 128) return;
    int k = idx >> 7, n = idx & 127;
    float v = src[k * 128 + n];
    __half h = __float2half_rn(v);
    __half l = __float2half_rn(v - __half2float(h));
    unsigned o = (unsigned)(k * 256 + (((n >> 3) ^ (k & 7)) * 16) + (n & 7) * 2);
    *(unsigned short*)(g_Bh + off + o) = __half_as_ushort(h);
    *(unsigned short*)(g_Bl + off + o) = __half_as_ushort(l);
}

// ------- fp16 mma.sync GEMM (2-pass: A*Bh + A*Bl): C[128,128]=A[128,K]@W ----
// 256 threads = 8 warps, warp grid 4(m) x 2(n): warp tile 32m x 64n.
// K staged in BK=64 chunks; A single fp16 image; B hi/lo fp16 images.
// __launch_bounds__(256,2) -> 2 CTAs/SM (regs<=128, smem 50KB).
// EPI 0: g_xw = C * dinv (pre-scaled xw').                (A=x, K=64)
// EPI 1: A = g_agg (h0); g_h1 = relu(C + g_b1f); stats[2],[3].   (K=128)
// EPI 2: g_xw = relu(C + cbias); stats[4],[5].            (A=action, K=32)
template<int K, int EPI>
__global__ void __launch_bounds__(256, 2)
k_bmma(const float* __restrict__ Aext, const float* __restrict__ cbias) {
    constexpr int BK    = (K < 64) ? K : 64;
    constexpr int NST   = K / BK;
    constexpr int CPR   = BK / 8;                   // 16B chunks per A row
    constexpr int AMASK = (CPR < 8 ? CPR : 8) - 1;
    constexpr int ASZ   = 128 * BK * 2;
    constexpr int BSZ   = BK * 128 * 2;
    extern __shared__ __align__(128) unsigned char smem[];
    unsigned char* A_im = smem;
    unsigned char* B_hi = smem + ASZ;
    unsigned char* B_lo = smem + ASZ + BSZ;
    float* s_sum = (float*)(smem + ASZ + 2 * BSZ);
    float* s_sq  = s_sum + H;

    const int tid   = threadIdx.x;
    const int lane  = tid & 31;
    const int wid   = tid >> 5;
    const int mwarp = wid & 3;
    const int nwarp = wid >> 2;
    const int bm    = blockIdx.x * 128;
    const float* A  = (EPI == 1) ? (const float*)g_agg : Aext;
    const int boff  = (EPI == 0) ? 0 : (EPI == 1) ? 16384 : 49152;

    if (EPI != 0 && tid < H) { s_sum[tid] = 0.f; s_sq[tid] = 0.f; }

    const unsigned uA  = smem_u32(A_im);
    const unsigned uBh = smem_u32(B_hi);
    const unsigned uBl = smem_u32(B_lo);

    float acc[2][8][4];
#pragma unroll
    for (int i = 0; i < 2; i++)
#pragma unroll
        for (int j = 0; j < 8; j++)
#pragma unroll
            for (int q = 0; q < 4; q++) acc[i][j][q] = 0.f;

    for (int st = 0; st < NST; st++) {
        if (st > 0) __syncthreads();    // protect buffers from previous mma

        {   // copy pre-swizzled B stage (L2-hot)
            const uint4* sh = (const uint4*)(g_Bh + boff + st * BK * 256);
            const uint4* sl = (const uint4*)(g_Bl + boff + st * BK * 256);
            uint4* dh = (uint4*)B_hi;
            uint4* dl = (uint4*)B_lo;
#pragma unroll
            for (int i = tid; i < BSZ / 16; i += 256) {
                dh[i] = sh[i]; dl[i] = sl[i];
            }
        }
        {   // build A fp16 image for this k-stage
            const int row0 = tid / CPR;
            const int c    = tid % CPR;
            const int kc   = st * BK + c * 8;
#pragma unroll
            for (int pass = 0; pass < CPR / 2; pass++) {
                int m  = row0 + pass * (256 / CPR);
                int gr = bm + m;
                float v[8];
                if (gr < NN) {
                    float4 x0 = *(const float4*)&A[(size_t)gr * K + kc];
                    float4 x1 = *(const float4*)&A[(size_t)gr * K + kc + 4];
                    v[0] = x0.x; v[1] = x0.y; v[2] = x0.z; v[3] = x0.w;
                    v[4] = x1.x; v[5] = x1.y; v[6] = x1.z; v[7] = x1.w;
                } else {
#pragma unroll
                    for (int j = 0; j < 8; j++) v[j] = 0.f;
                }
                uint4 hp;
                hp.x = h2pack(v[0], v[1]);
                hp.y = h2pack(v[2], v[3]);
                hp.z = h2pack(v[4], v[5]);
                hp.w = h2pack(v[6], v[7]);
                unsigned o = (unsigned)(m * (BK * 2) + ((c ^ (m & AMASK)) * 16));
                *(uint4*)(A_im + o) = hp;
            }
        }
        __syncthreads();

#pragma unroll
        for (int k16 = 0; k16 < BK / 16; k16++) {
            unsigned ah[2][4];
#pragma unroll
            for (int mf = 0; mf < 2; mf++) {
                int row = mwarp * 32 + mf * 16 + (lane & 15);
                int c   = 2 * k16 + (lane >> 4);
                unsigned o = (unsigned)(row * (BK * 2) + ((c ^ (row & AMASK)) * 16));
                LDSM4(ah[mf][0], ah[mf][1], ah[mf][2], ah[mf][3], uA + o);
            }
#pragma unroll
            for (int g = 0; g < 4; g++) {
                int row = k16 * 16 + (lane & 15);
                int c   = nwarp * 8 + g * 2 + (lane >> 4);
                unsigned o = (unsigned)(row * 256 + ((c ^ (row & 7)) * 16));
                unsigned r0, r1, r2, r3;
                unsigned b0[2], b1[2];
                LDSM4T(r0, r1, r2, r3, uBh + o);
                b0[0] = r0; b0[1] = r1; b1[0] = r2; b1[1] = r3;
#pragma unroll
                for (int mf = 0; mf < 2; mf++) {
                    hmma(acc[mf][2 * g],     ah[mf], b0);
                    hmma(acc[mf][2 * g + 1], ah[mf], b1);
                }
                LDSM4T(r0, r1, r2, r3, uBl + o);
                b0[0] = r0; b0[1] = r1; b1[0] = r2; b1[1] = r3;
#pragma unroll
                for (int mf = 0; mf < 2; mf++) {
                    hmma(acc[mf][2 * g],     ah[mf], b0);
                    hmma(acc[mf][2 * g + 1], ah[mf], b1);
                }
            }
        }
    }

    const int qr = lane >> 2;
    const int qc = (lane & 3) * 2;
    if (EPI == 0) {
#pragma unroll
        for (int mf = 0; mf < 2; mf++) {
            int m1 = bm + mwarp * 32 + mf * 16 + qr;
            int m2 = m1 + 8;
            float d1 = (m1 < NN) ? g_deg[m1] : 0.f;   // dinv
            float d2 = (m2 < NN) ? g_deg[m2] : 0.f;
#pragma unroll
            for (int nf = 0; nf < 8; nf++) {
                int n = nwarp * 64 + nf * 8 + qc;
                float* c4 = acc[mf][nf];
                if (m1 < NN)
                    *(float2*)&g_xw[(size_t)m1 * H + n] =
                        make_float2(c4[0] * d1, c4[1] * d1);
                if (m2 < NN)
                    *(float2*)&g_xw[(size_t)m2 * H + n] =
                        make_float2(c4[2] * d2, c4[3] * d2);
            }
        }
    } else {
        float* dst = (EPI == 1) ? (float*)g_h1 : (float*)g_xw;
        const float* cb = (EPI == 1) ? (const float*)g_b1f : cbias;
        float fs[8][2], fq[8][2];
#pragma unroll
        for (int nf = 0; nf < 8; nf++) {
            fs[nf][0] = fs[nf][1] = 0.f;
            fq[nf][0] = fq[nf][1] = 0.f;
        }
#pragma unroll
        for (int mf = 0; mf < 2; mf++) {
            int m1 = bm + mwarp * 32 + mf * 16 + qr;
            int m2 = m1 + 8;
#pragma unroll
            for (int nf = 0; nf < 8; nf++) {
                int n = nwarp * 64 + nf * 8 + qc;
                float2 bb = *(const float2*)&cb[n];
                float* c4 = acc[mf][nf];
                float v0 = fmaxf(c4[0] + bb.x, 0.f);
                float v1 = fmaxf(c4[1] + bb.y, 0.f);
                float v2 = fmaxf(c4[2] + bb.x, 0.f);
                float v3 = fmaxf(c4[3] + bb.y, 0.f);
                if (m1 < NN)
                    *(float2*)&dst[(size_t)m1 * H + n] = make_float2(v0, v1);
                else { v0 = 0.f; v1 = 0.f; }
                if (m2 < NN)
                    *(float2*)&dst[(size_t)m2 * H + n] = make_float2(v2, v3);
                else { v2 = 0.f; v3 = 0.f; }
                fs[nf][0] += v0 + v2; fs[nf][1] += v1 + v3;
                fq[nf][0] += v0 * v0 + v2 * v2;
                fq[nf][1] += v1 * v1 + v3 * v3;
            }
        }
#pragma unroll
        for (int off = 4; off <= 16; off <<= 1)
#pragma unroll
            for (int nf = 0; nf < 8; nf++)
#pragma unroll
                for (int j = 0; j < 2; j++) {
                    fs[nf][j] += __shfl_down_sync(0xffffffffu, fs[nf][j], off);
                    fq[nf][j] += __shfl_down_sync(0xffffffffu, fq[nf][j], off);
                }
        if (lane < 4) {
#pragma unroll
            for (int nf = 0; nf < 8; nf++) {
                int n = nwarp * 64 + nf * 8 + lane * 2;
                atomicAdd(&s_sum[n],     fs[nf][0]);
                atomicAdd(&s_sum[n + 1], fs[nf][1]);
                atomicAdd(&s_sq[n],      fq[nf][0]);
                atomicAdd(&s_sq[n + 1],  fq[nf][1]);
            }
        }
        __syncthreads();
        if (tid < H) {
            const int soff = (EPI == 1) ? 2 : 4;
            atomicAdd(&g_stats[(size_t)soff * H + tid], (double)s_sum[tid]);
            atomicAdd(&g_stats[(size_t)(soff + 1) * H + tid], (double)s_sq[tid]);
        }
    }
}

// ---------------- pull-mode GCN aggregate + h0 + BN0 stats -------------------
__global__ void __launch_bounds__(256) k_gather(const float* __restrict__ bgcn) {
    __shared__ float s_sum[H], s_sq[H];
    const int tid = threadIdx.x, lane = tid & 31, wid = tid >> 5;
    if (tid < H) { s_sum[tid] = 0.f; s_sq[tid] = 0.f; }
    __syncthreads();

    const float4 b4 = *(const float4*)&bgcn[lane * 4];
    float fs[4] = {0, 0, 0, 0}, fq[4] = {0, 0, 0, 0};
    const int step = gridDim.x * 8;

    for (int node = blockIdx.x * 8 + wid; node < NN; node += step) {
        float4 acc = *(const float4*)&g_xw[(size_t)node * H + lane * 4];
        const int base = g_off[node];
        const int cnt  = g_cnt[node];
        for (int c0 = 0; c0 < cnt; c0 += 32) {
            int n = min(cnt - c0, 32);
            int idx = (lane < n) ? g_ssrc[base + c0 + lane] : 0;
            int sc = __shfl_sync(0xffffffffu, idx, 0);
            float4 v = *(const float4*)&g_xw[(size_t)sc * H + lane * 4];
            for (int i = 0; i < n; i++) {
                float4 cur = v;
                if (i + 1 < n) {
                    int sn = __shfl_sync(0xffffffffu, idx, i + 1);
                    v = *(const float4*)&g_xw[(size_t)sn * H + lane * 4];
                }
                acc.x += cur.x; acc.y += cur.y; acc.z += cur.z; acc.w += cur.w;
            }
        }
        const float dv = g_deg[node];
        float h0x = fmaxf(acc.x * dv + b4.x, 0.f);
        float h0y = fmaxf(acc.y * dv + b4.y, 0.f);
        float h0z = fmaxf(acc.z * dv + b4.z, 0.f);
        float h0w = fmaxf(acc.w * dv + b4.w, 0.f);
        *(float4*)&g_agg[(size_t)node * H + lane * 4] =
            make_float4(h0x, h0y, h0z, h0w);
        fs[0] += h0x; fs[1] += h0y; fs[2] += h0z; fs[3] += h0w;
        fq[0] += h0x * h0x; fq[1] += h0y * h0y;
        fq[2] += h0z * h0z; fq[3] += h0w * h0w;
    }

#pragma unroll
    for (int j = 0; j < 4; j++) {
        atomicAdd(&s_sum[lane * 4 + j], fs[j]);
        atomicAdd(&s_sq[lane * 4 + j], fq[j]);
    }
    __syncthreads();
    if (tid < H) {
        atomicAdd(&g_stats[0 * H + tid], (double)s_sum[tid]);
        atomicAdd(&g_stats[1 * H + tid], (double)s_sq[tid]);
    }
}

// ------------------------- fold BN0 into W1 ----------------------------------
__global__ void k_fold1(const float* __restrict__ g0, const float* __restrict__ be0,
                        const float* __restrict__ W1, const float* __restrict__ b1) {
    __shared__ float s0[H], t0[H];
    const int f = threadIdx.x;
    double mu  = g_stats[0 * H + f] / (double)NN;
    double var = g_stats[1 * H + f] / (double)NN - mu * mu;
    float  r   = (float)(1.0 / sqrt(var + 1e-5));
    float  sf  = g0[f] * r;
    float  tf  = be0[f] - (float)mu * sf;
    s0[f] = sf; t0[f] = tf;
    __syncthreads();
    float bacc = b1[f];
    for (int k = 0; k < H; k++) {
        float w = W1[k * H + f];
        g_W1f[k * H + f] = s0[k] * w;
        bacc += t0[k] * w;
    }
    g_b1f[f] = bacc;
}

// ------------------------- fold BN1/BN2 + W3 ---------------------------------
__global__ void k_fold3(const float* __restrict__ g1, const float* __restrict__ be1,
                        const float* __restrict__ g2, const float* __restrict__ be2,
                        const float* __restrict__ W3, const float* __restrict__ b3) {
    const int f = threadIdx.x;
    double mu1 = g_stats[2 * H + f] / (double)NN;
    double v1  = g_stats[3 * H + f] / (double)NN - mu1 * mu1;
    float  r1  = (float)(1.0 / sqrt(v1 + 1e-5));
    float  s1  = g1[f] * r1;
    float  t1  = be1[f] - (float)mu1 * s1;
    double mu2 = g_stats[4 * H + f] / (double)NN;
    double v2  = g_stats[5 * H + f] / (double)NN - mu2 * mu2;
    float  r2  = (float)(1.0 / sqrt(v2 + 1e-5));
    float  s2  = g2[f] * r2;
    float  t2  = be2[f] - (float)mu2 * s2;
    float w3a = W3[f], w3b = W3[H + f];
    g_W3a[f] = w3a * s1;
    g_W3b[f] = w3b * s2;
    __shared__ double red[H];
    red[f] = (double)(t1 * w3a) + (double)(t2 * w3b);
    __syncthreads();
    for (int o = 64; o > 0; o >>= 1) {
        if (f < o) red[f] += red[f + o];
        __syncthreads();
    }
    if (f == 0) g_c = (float)red[0] + b3[0];
}

// ------------------------- per-node scalar + segment sum ---------------------
__global__ void k_z(const long long* __restrict__ b64, const int* __restrict__ b32) {
    const int is64 = g_is64;
    const int lane = threadIdx.x & 31;
    const int n    = (blockIdx.x * blockDim.x + threadIdx.x) >> 5;
    if (n >= NN) return;
    float4 a  = *(const float4*)&g_h1[(size_t)n * H + lane * 4];
    float4 b  = *(const float4*)&g_xw[(size_t)n * H + lane * 4];   // h2
    float4 wa = *(const float4*)&g_W3a[lane * 4];
    float4 wb = *(const float4*)&g_W3b[lane * 4];
    float z = a.x * wa.x + a.y * wa.y + a.z * wa.z + a.w * wa.w +
              b.x * wb.x + b.y * wb.y + b.z * wb.z + b.w * wb.w;
#pragma unroll
    for (int o = 16; o > 0; o >>= 1) z += __shfl_xor_sync(0xffffffffu, z, o);
    if (lane == 0) {
        int g = is64 ? (int)b64[n] : b32[n];
        atomicAdd(&g_gsum[g], z);
        atomicAdd(&g_gcnt[g], 1.0f);
    }
}

__global__ void k_final(float* __restrict__ out, const float* __restrict__ b3) {
    int b = blockIdx.x * blockDim.x + threadIdx.x;
    if (b < NB) {
        float c = g_gcnt[b];
        out[b] = (c > 0.f) ? (g_gsum[b] / c + g_c) : b3[0];
    }
}

// ------------------------- launch ---------------------------------------------
extern "C" void kernel_launch(void* const* d_in, const int* in_sizes, int n_in,
                              void* d_out, int out_size) {
    const float* x      = (const float*)d_in[0];
    const float* action = (const float*)d_in[1];
    const float* W_gcn  = (const float*)d_in[2];
    const float* b_gcn  = (const float*)d_in[3];
    const float* g0     = (const float*)d_in[4];
    const float* be0    = (const float*)d_in[5];
    const float* W1     = (const float*)d_in[6];
    const float* b1     = (const float*)d_in[7];
    const float* g1     = (const float*)d_in[8];
    const float* be1    = (const float*)d_in[9];
    const float* W2     = (const float*)d_in[10];
    const float* b2     = (const float*)d_in[11];
    const float* g2     = (const float*)d_in[12];
    const float* be2    = (const float*)d_in[13];
    const float* W3     = (const float*)d_in[14];
    const float* b3     = (const float*)d_in[15];
    const long long* e64 = (const long long*)d_in[16];
    const int*       e32 = (const int*)d_in[16];
    const long long* bt64 = (const long long*)d_in[17];
    const int*       bt32 = (const int*)d_in[17];
    float* out = (float*)d_out;

    const int GBLK = (NN + 127) / 128;   // 1563
    // smem: ASZ + 2*BSZ + 1024, BK=min(K,64)
    const int SM64  = (128 * 64 * 2) + 2 * (64 * 128 * 2) + 1024;  // 50176
    const int SM128 = SM64;                                        // staged
    const int SM32  = (128 * 32 * 2) + 2 * (32 * 128 * 2) + 1024;  // 25600

    cudaFuncSetAttribute(k_bmma<64, 0>,
                         cudaFuncAttributeMaxDynamicSharedMemorySize, SM64);
    cudaFuncSetAttribute(k_bmma<128, 1>,
                         cudaFuncAttributeMaxDynamicSharedMemorySize, SM128);
    cudaFuncSetAttribute(k_bmma<32, 2>,
                         cudaFuncAttributeMaxDynamicSharedMemorySize, SM32);

    k_detect<<<1, 32>>>(e64);
    k_init<<<(NN + 255) / 256, 256>>>();
    k_hist<<<1024, 256>>>(e64, e32);
    k_scan1<<<NBLK, 256>>>();
    k_scan2<<<1, 256>>>();
    k_scan3<<<NBLK, 256>>>();
    k_sortedges<<<1024, 256>>>(e64, e32);
    k_prep<0><<<32, 256>>>(W_gcn);
    k_prep<2><<<16, 256>>>(W2);
    k_bmma<64, 0><<<GBLK, 256, SM64>>>(x, nullptr);         // xw' = dinv * xW
    k_gather<<<1536, 256>>>(b_gcn);                         // h0 + BN0 stats
    k_fold1<<<1, H>>>(g0, be0, W1, b1);
    k_prep<1><<<64, 256>>>(nullptr);                        // W1f -> fp16
    k_bmma<128, 1><<<GBLK, 256, SM128>>>(nullptr, nullptr); // h1
    k_bmma<32, 2><<<GBLK, 256, SM32>>>(action, b2);         // h2 -> g_xw
    k_fold3<<<1, H>>>(g1, be1, g2, be2, W3, b3);
    k_z<<<NN / 8, 256>>>(bt64, bt32);
    k_final<<<4, 256>>>(out, b3);
}